// round 4
// baseline (speedup 1.0000x reference)
#include <cuda_runtime.h>

#define DINLINE __device__ __forceinline__

namespace {
constexpr int L = 160, H = 128, HP = 129, R = 4, BATCH = 2;
constexpr int D = 768;
constexpr int NKJ = H * HP;                 // 16512
constexpr long long WTRI_RSTRIDE = (long long)HP * NKJ;  // 2130048

// arena offsets (floats). V and S share [0..); logits and SP share [V_SZ..)
constexpr long long V_SZ  = (long long)BATCH * R * L * L * HP;  // 26,419,200
constexpr long long LG_SZ = (long long)BATCH * R * L * L * L;   // 32,768,000
constexpr long long OFF_V  = 0;
constexpr long long OFF_LG = V_SZ;
constexpr long long OFF_S  = 0;                                  // reuses V
constexpr long long OFF_SP = V_SZ;                               // reuses logits
constexpr long long ARENA_SZ = V_SZ + LG_SZ;                     // 59,187,200
}

// ------------------------- static device scratch ----------------------------
__device__ float g_hidden[BATCH * L * 4 * H];    // [b*L+l][512]
__device__ float g_scoring[BATCH * L * 2 * H];   // [b*L+l][256]
__device__ float g_tailP[BATCH * L * HP];        // [b*L+y][i], i=128 -> 1
__device__ float g_xheadP[BATCH * L * HP];       // [b*L+x][n], n=128 -> 1
__device__ float g_inPT[BATCH * HP * L];         // [b][j][z], j=128 -> 1
__device__ float g_xtailPT[BATCH * HP * L];      // [b][m][y], m=128 -> 1
__device__ float g_U[(long long)BATCH * R * L * NKJ];   // [(b*4+r)*160+y][k*129+j]
__device__ float g_G[(long long)BATCH * L * NKJ];       // [b][x][q*129+m]
__device__ float g_Gt2[(long long)BATCH * L * H * L];   // [b][x*128+q][y]
__device__ float g_arena[ARENA_SZ];

DINLINE float leaky(float v) { return v >= 0.f ? v : 0.1f * v; }

// ------------------- generic batched GEMM: C = A @ B ------------------------
// A[M,K] lda, B[K,N] ldb, C[M,N] ldc; per-batch pointer strides sA,sB,sC.
// ep==1: C = leaky(acc + bias[n]). Bounds-checked everywhere; K zero-padded.
__global__ __launch_bounds__(256) void gemm_k(
    const float* __restrict__ A, const float* __restrict__ B,
    float* __restrict__ C, int M, int N, int K, int lda, int ldb, int ldc,
    long long sA, long long sB, long long sC, int ep,
    const float* __restrict__ bias) {
  A += (long long)blockIdx.z * sA;
  B += (long long)blockIdx.z * sB;
  C += (long long)blockIdx.z * sC;
  __shared__ float As[16][64];
  __shared__ float Bs[16][64];
  const int tid = threadIdx.x;
  const int tx = tid & 15, ty = tid >> 4;
  const int m0 = blockIdx.y * 64, n0 = blockIdx.x * 64;
  float acc[4][4] = {};
  for (int k0 = 0; k0 < K; k0 += 16) {
#pragma unroll
    for (int t = 0; t < 4; ++t) {
      int li = tid + t * 256;
      int k = li >> 6, mn = li & 63;
      As[k][mn] = (m0 + mn < M && k0 + k < K)
                      ? A[(long long)(m0 + mn) * lda + (k0 + k)] : 0.f;
      Bs[k][mn] = (n0 + mn < N && k0 + k < K)
                      ? B[(long long)(k0 + k) * ldb + (n0 + mn)] : 0.f;
    }
    __syncthreads();
#pragma unroll
    for (int k = 0; k < 16; ++k) {
      float4 av = *(const float4*)(&As[k][ty * 4]);
      float4 bv = *(const float4*)(&Bs[k][tx * 4]);
      acc[0][0] = fmaf(av.x, bv.x, acc[0][0]);
      acc[0][1] = fmaf(av.x, bv.y, acc[0][1]);
      acc[0][2] = fmaf(av.x, bv.z, acc[0][2]);
      acc[0][3] = fmaf(av.x, bv.w, acc[0][3]);
      acc[1][0] = fmaf(av.y, bv.x, acc[1][0]);
      acc[1][1] = fmaf(av.y, bv.y, acc[1][1]);
      acc[1][2] = fmaf(av.y, bv.z, acc[1][2]);
      acc[1][3] = fmaf(av.y, bv.w, acc[1][3]);
      acc[2][0] = fmaf(av.z, bv.x, acc[2][0]);
      acc[2][1] = fmaf(av.z, bv.y, acc[2][1]);
      acc[2][2] = fmaf(av.z, bv.z, acc[2][2]);
      acc[2][3] = fmaf(av.z, bv.w, acc[2][3]);
      acc[3][0] = fmaf(av.w, bv.x, acc[3][0]);
      acc[3][1] = fmaf(av.w, bv.y, acc[3][1]);
      acc[3][2] = fmaf(av.w, bv.z, acc[3][2]);
      acc[3][3] = fmaf(av.w, bv.w, acc[3][3]);
    }
    __syncthreads();
  }
#pragma unroll
  for (int ii = 0; ii < 4; ++ii) {
    int m = m0 + ty * 4 + ii;
    if (m >= M) continue;
#pragma unroll
    for (int jj = 0; jj < 4; ++jj) {
      int n = n0 + tx * 4 + jj;
      if (n >= N) continue;
      float v = acc[ii][jj];
      if (ep == 1) v = leaky(v + bias[n]);
      C[(long long)m * ldc + n] = v;
    }
  }
}

// ---------------- prep: padded splits / transposes --------------------------
// tailP, xheadP, inPT, xtailPT. One thread per element, range dispatch.
__global__ void k_prep() {
  int t = blockIdx.x * blockDim.x + threadIdx.x;
  const int NPAD = BATCH * L * HP;  // 41280
  if (t < NPAD) {
    int row = t / HP, i = t % HP;
    g_tailP[t] = (i < H) ? g_hidden[(long long)row * (4 * H) + 2 * H + i] : 1.f;
    return;
  }
  t -= NPAD;
  if (t < NPAD) {
    int row = t / HP, n = t % HP;
    g_xheadP[t] = (n < H) ? g_scoring[(long long)row * (2 * H) + n] : 1.f;
    return;
  }
  t -= NPAD;
  if (t < NPAD) {  // inPT[b][j][z]
    int b = t / (HP * L), rem = t % (HP * L);
    int j = rem / L, z = rem % L;
    g_inPT[t] = (j < H)
        ? g_hidden[(long long)(b * L + z) * (4 * H) + 3 * H + j] : 1.f;
    return;
  }
  t -= NPAD;
  if (t < NPAD) {  // xtailPT[b][m][y]
    int b = t / (HP * L), rem = t % (HP * L);
    int m = rem / L, y = rem % L;
    g_xtailPT[t] = (m < H)
        ? g_scoring[(long long)(b * L + y) * (2 * H) + H + m] : 1.f;
  }
}

// ---------------- softmax over last dim (160) of logits rows ----------------
__global__ void k_softmax(float* __restrict__ lg, int nrows) {
  int w = (blockIdx.x * blockDim.x + threadIdx.x) >> 5;
  int lane = threadIdx.x & 31;
  if (w >= nrows) return;
  float* row = lg + (long long)w * L;
  float v[5];
  float mx = -1e30f;
#pragma unroll
  for (int t = 0; t < 5; ++t) {
    v[t] = row[t * 32 + lane];
    mx = fmaxf(mx, v[t]);
  }
#pragma unroll
  for (int o = 16; o; o >>= 1) mx = fmaxf(mx, __shfl_xor_sync(0xffffffffu, mx, o));
  float s = 0.f;
#pragma unroll
  for (int t = 0; t < 5; ++t) { v[t] = __expf(v[t] - mx); s += v[t]; }
#pragma unroll
  for (int o = 16; o; o >>= 1) s += __shfl_xor_sync(0xffffffffu, s, o);
  float inv = 1.f / s;
#pragma unroll
  for (int t = 0; t < 5; ++t) row[t * 32 + lane] = v[t] * inv;
}

// -------- score[b,r,x,y] = sum_q SP[b,r,y,x,q] * Gt2[b][x*128+q][y] ---------
__global__ void k_score(const float* __restrict__ SP,
                        const float* __restrict__ Gt2,
                        float* __restrict__ out) {
  int w = (blockIdx.x * blockDim.x + threadIdx.x) >> 5;
  int lane = threadIdx.x & 31;
  if (w >= BATCH * R * L * L) return;
  int y = w % L;
  int t = w / L;
  int x = t % L; t /= L;
  int r = t % R;
  int b = t / R;
  const float* sp = SP + ((long long)((b * R + r) * L + y) * L + x) * H;
  const float* gt = Gt2 + (long long)b * (L * H) * L;
  float s = 0.f;
#pragma unroll
  for (int qq = 0; qq < 4; ++qq) {
    int q = lane + qq * 32;
    s += sp[q] * gt[(long long)(x * H + q) * L + y];
  }
#pragma unroll
  for (int o = 16; o; o >>= 1) s += __shfl_xor_sync(0xffffffffu, s, o);
  if (lane == 0) out[((long long)(b * R + r) * L + x) * L + y] = s;
}

// ------------------------------- launch --------------------------------------
static const float* pick_by_size(void* const* d_in, const int* in_sizes,
                                 int n_in, int want, int fallback_idx) {
  for (int i = 0; i < n_in; ++i)
    if (in_sizes[i] == want) return (const float*)d_in[i];
  return (const float*)d_in[fallback_idx];
}

static inline dim3 gemm_grid(int M, int N, int batches) {
  return dim3((N + 63) / 64, (M + 63) / 64, batches);
}

extern "C" void kernel_launch(void* const* d_in, const int* in_sizes, int n_in,
                              void* d_out, int out_size) {
  (void)out_size;
  const float* x      = pick_by_size(d_in, in_sizes, n_in, BATCH * L * D, 0);
  const float* Wspan  = pick_by_size(d_in, in_sizes, n_in, D * 4 * H, 1);
  const float* bspan  = pick_by_size(d_in, in_sizes, n_in, 4 * H, 2);
  const float* Wscore = pick_by_size(d_in, in_sizes, n_in, D * 2 * H, 3);
  const float* bscore = pick_by_size(d_in, in_sizes, n_in, 2 * H, 4);
  const float* Wtri   = pick_by_size(d_in, in_sizes, n_in, R * HP * H * HP, 5);
  const float* Wmlp   = pick_by_size(d_in, in_sizes, n_in, H * H, 6);
  const float* bmlp   = pick_by_size(d_in, in_sizes, n_in, H, 7);
  const float* Wfin   = pick_by_size(d_in, in_sizes, n_in, HP * H * HP, 8);
  float* out = (float*)d_out;

  float* d_hidden;  cudaGetSymbolAddress((void**)&d_hidden, g_hidden);
  float* d_scoring; cudaGetSymbolAddress((void**)&d_scoring, g_scoring);
  float* d_tailP;   cudaGetSymbolAddress((void**)&d_tailP, g_tailP);
  float* d_xheadP;  cudaGetSymbolAddress((void**)&d_xheadP, g_xheadP);
  float* d_inPT;    cudaGetSymbolAddress((void**)&d_inPT, g_inPT);
  float* d_xtailPT; cudaGetSymbolAddress((void**)&d_xtailPT, g_xtailPT);
  float* d_U;       cudaGetSymbolAddress((void**)&d_U, g_U);
  float* d_G;       cudaGetSymbolAddress((void**)&d_G, g_G);
  float* d_Gt2;     cudaGetSymbolAddress((void**)&d_Gt2, g_Gt2);
  float* d_arena;   cudaGetSymbolAddress((void**)&d_arena, g_arena);
  float* d_V  = d_arena + OFF_V;
  float* d_LG = d_arena + OFF_LG;
  float* d_S  = d_arena + OFF_S;
  float* d_SP = d_arena + OFF_SP;

  const int BLrows = BATCH * L;  // 320

  // 1) hidden = leaky(x @ Wspan + bspan)   [320,512]
  gemm_k<<<gemm_grid(BLrows, 4 * H, 1), 256>>>(
      x, Wspan, d_hidden, BLrows, 4 * H, D, D, 4 * H, 4 * H, 0, 0, 0, 1, bspan);
  // 2) scoring = leaky(x @ Wscore + bscore) [320,256]
  gemm_k<<<gemm_grid(BLrows, 2 * H, 1), 256>>>(
      x, Wscore, d_scoring, BLrows, 2 * H, D, D, 2 * H, 2 * H, 0, 0, 0, 1, bscore);
  // 3) padded splits / transposes
  k_prep<<<(4 * BATCH * L * HP + 255) / 256, 256>>>();
  // 4) U[(b,r)][y][k*129+j] = tailP[b,y,:] @ Wtri[r]   (8 calls)
  for (int b = 0; b < BATCH; ++b)
    for (int r = 0; r < R; ++r)
      gemm_k<<<gemm_grid(L, NKJ, 1), 256>>>(
          d_tailP + (long long)b * L * HP, Wtri + (long long)r * WTRI_RSTRIDE,
          d_U + (long long)(b * R + r) * L * NKJ,
          L, NKJ, HP, HP, NKJ, NKJ, 0, 0, 0, 0, nullptr);
  // 5) G[b][x][q*129+m] = xheadP[b,x,:] @ Wfin
  for (int b = 0; b < BATCH; ++b)
    gemm_k<<<gemm_grid(L, NKJ, 1), 256>>>(
        d_xheadP + (long long)b * L * HP, Wfin, d_G + (long long)b * L * NKJ,
        L, NKJ, HP, HP, NKJ, NKJ, 0, 0, 0, 0, nullptr);
  // 6) Gt2[b][xq][y] = G[b](as [20480,129]) @ xtailPT[b] [129,160]
  for (int b = 0; b < BATCH; ++b)
    gemm_k<<<gemm_grid(L * H, L, 1), 256>>>(
        d_G + (long long)b * L * NKJ, d_xtailPT + (long long)b * HP * L,
        d_Gt2 + (long long)b * (L * H) * L,
        L * H, L, HP, HP, L, L, 0, 0, 0, 0, nullptr);
  // 7) V[b][z=(r,y)][x][j] = head[b] [160,128] @ U[(b,z)] [128,129]
  for (int b = 0; b < BATCH; ++b)
    gemm_k<<<gemm_grid(L, HP, R * L), 256>>>(
        d_hidden + (long long)b * L * (4 * H) + H,
        d_U + (long long)b * R * L * NKJ,
        d_V + (long long)b * R * L * (L * HP),
        L, HP, H, 4 * H, HP, HP,
        0, NKJ, (long long)L * HP, 0, nullptr);
  // 8) logits[b][z][x][zz] = V[b][z] [160,129] @ inPT[b] [129,160]
  for (int b = 0; b < BATCH; ++b)
    gemm_k<<<gemm_grid(L, L, R * L), 256>>>(
        d_V + (long long)b * R * L * (L * HP), d_inPT + (long long)b * HP * L,
        d_LG + (long long)b * R * L * (L * L),
        L, L, HP, HP, L, L,
        (long long)L * HP, 0, (long long)L * L, nullptr ? 0 : 0, nullptr);
  // 9) softmax over z (in place)
  {
    int nrows = BATCH * R * L * L;
    k_softmax<<<(nrows * 32 + 255) / 256, 256>>>(d_LG, nrows);
  }
  // 10) S[b][z][x][h] = alpha[b][z] [160,160] @ HinRepr[b] [160,128]
  for (int b = 0; b < BATCH; ++b)
    gemm_k<<<gemm_grid(L, H, R * L), 256>>>(
        d_LG + (long long)b * R * L * (L * L),
        d_hidden + (long long)b * L * (4 * H),
        d_S + (long long)b * R * L * (L * H),
        L, H, L, L, 4 * H, H,
        (long long)L * L, 0, (long long)L * H, 0, nullptr);
  // 11) SP = leaky(S @ Wmlp + bmlp)  [204800,128]
  gemm_k<<<gemm_grid(BATCH * R * L * L, H, 1), 256>>>(
      d_S, Wmlp, d_SP, BATCH * R * L * L, H, H, H, H, H, 0, 0, 0, 1, bmlp);
  // 12) score
  {
    int nwarps = BATCH * R * L * L;
    k_score<<<(nwarps * 32 + 255) / 256, 256>>>(d_SP, d_Gt2, out);
  }
}

// round 5
// speedup vs baseline: 1.1565x; 1.1565x over previous
#include <cuda_runtime.h>

#define DINLINE __device__ __forceinline__

namespace {
constexpr int L = 160, H = 128, HP = 129, R = 4, BATCH = 2, D = 768;
constexpr int NKJ = H * HP;                              // 16512
constexpr long long WTRI_R = (long long)HP * NKJ;        // 2130048

constexpr long long V_SZ  = (long long)BATCH * R * L * L * HP;  // 26,419,200
constexpr long long LG_SZ = (long long)BATCH * R * L * L * L;   // 32,768,000
constexpr long long OFF_V  = 0;        // W2 lives here, later S
constexpr long long OFF_LG = V_SZ;     // logits, later SP
constexpr long long ARENA_SZ = V_SZ + LG_SZ;
constexpr long long W2_B = (long long)R * L * H * L;     // 13,107,200 per b
constexpr long long S_B  = (long long)R * L * L * H;     // 13,107,200 per b
constexpr long long LG_B = (long long)R * L * L * L;     // 16,384,000 per b
}

// ------------------------- static device scratch ----------------------------
__device__ float g_hidden[BATCH * L * 4 * H];    // [b*L+l][512]
__device__ float g_scoring[BATCH * L * 2 * H];   // [b*L+l][256]
__device__ float g_tailP[BATCH * L * HP];        // [b*L+y][i], i=128 -> 1
__device__ float g_xheadP[BATCH * L * HP];       // [b*L+x][n], n=128 -> 1
__device__ float g_inPT[BATCH * HP * L];         // [b][j][z], j=128 -> 1
__device__ float g_xtailPT[BATCH * HP * L];      // [b][m][y], m=128 -> 1
__device__ float g_U[(long long)BATCH * R * L * NKJ];   // [(b*R+r)*L+y][k*129+j]
__device__ float g_G[(long long)BATCH * L * NKJ];       // [b][x][q*129+m]
__device__ float g_Gt2[(long long)BATCH * L * H * L];   // [b][x*128+q][y]
__device__ float g_Gt3[(long long)BATCH * L * L * H];   // [b][y][x*128+q]
__device__ float g_arena[ARENA_SZ];

DINLINE float leaky(float v) { return v >= 0.f ? v : 0.1f * v; }

// ---------------- templated GEMM: C = A @ B, 8x8 split microtile -------------
// A[M,K] lda, B[K,N] ldb, C[M,N] ldc; batch strides sA,sB,sC over blockIdx.z.
// ep==1: C = leaky(acc + bias[n]). K zero-padded via load guards.
// Thread layout: tx = tid % (BN/8) (cols), ty = tid / (BN/8) (rows).
// Each thread: rows {ty*4..+3} U {BM/2+ty*4..+3}, cols {tx*4..+3} U {BN/2+tx*4..+3}.
template <int BM, int BN>
__global__ void __launch_bounds__((BM / 8) * (BN / 8)) gemm_t(
    const float* __restrict__ A, const float* __restrict__ B,
    float* __restrict__ C, int M, int N, int K, int lda, int ldb, int ldc,
    long long sA, long long sB, long long sC, int ep,
    const float* __restrict__ bias) {
  constexpr int NT = (BM / 8) * (BN / 8);
  constexpr int AST = BM + 4;  // padded stride (mult of 4, dodges bank conflicts)
  __shared__ float As[16][AST];  // transposed: As[k][m]
  __shared__ float Bs[16][BN];   // Bs[k][n]
  A += (long long)blockIdx.z * sA;
  B += (long long)blockIdx.z * sB;
  C += (long long)blockIdx.z * sC;
  const int tid = threadIdx.x;
  const int tx = tid % (BN / 8), ty = tid / (BN / 8);
  const int m0 = blockIdx.y * BM, n0 = blockIdx.x * BN;
  float acc[8][8] = {};

  for (int k0 = 0; k0 < K; k0 += 16) {
    __syncthreads();  // previous compute done before overwriting tiles
    // A tile: scalar loads (works for any lda), transposed store
    for (int idx = tid; idx < BM * 16; idx += NT) {
      int m = idx >> 4, k = idx & 15;
      float v = 0.f;
      if (k0 + k < K && m0 + m < M)
        v = A[(long long)(m0 + m) * lda + (k0 + k)];
      As[k][m] = v;
    }
    // B tile: float4 loads (all ldb are multiples of 4)
    for (int idx = tid; idx < BN * 4; idx += NT) {
      int k = idx / (BN / 4), n4 = idx % (BN / 4);
      float4 v = make_float4(0.f, 0.f, 0.f, 0.f);
      if (k0 + k < K)
        v = *(const float4*)(B + (long long)(k0 + k) * ldb + n0 + n4 * 4);
      *(float4*)(&Bs[k][n4 * 4]) = v;
    }
    __syncthreads();
#pragma unroll
    for (int k = 0; k < 16; ++k) {
      float4 A0 = *(const float4*)(&As[k][ty * 4]);
      float4 A1 = *(const float4*)(&As[k][BM / 2 + ty * 4]);
      float4 B0 = *(const float4*)(&Bs[k][tx * 4]);
      float4 B1 = *(const float4*)(&Bs[k][BN / 2 + tx * 4]);
      float av[8] = {A0.x, A0.y, A0.z, A0.w, A1.x, A1.y, A1.z, A1.w};
      float bv[8] = {B0.x, B0.y, B0.z, B0.w, B1.x, B1.y, B1.z, B1.w};
#pragma unroll
      for (int i = 0; i < 8; ++i)
#pragma unroll
        for (int j = 0; j < 8; ++j)
          acc[i][j] = fmaf(av[i], bv[j], acc[i][j]);
    }
  }
  // epilogue
#pragma unroll
  for (int i = 0; i < 8; ++i) {
    int m = m0 + (i < 4 ? ty * 4 + i : BM / 2 + ty * 4 + (i - 4));
    if (m >= M) continue;
#pragma unroll
    for (int jh = 0; jh < 2; ++jh) {
      int n = n0 + (jh ? BN / 2 : 0) + tx * 4;
      float4 v = make_float4(acc[i][jh * 4 + 0], acc[i][jh * 4 + 1],
                             acc[i][jh * 4 + 2], acc[i][jh * 4 + 3]);
      if (ep == 1) {
        v.x = leaky(v.x + bias[n + 0]);
        v.y = leaky(v.y + bias[n + 1]);
        v.z = leaky(v.z + bias[n + 2]);
        v.w = leaky(v.w + bias[n + 3]);
      }
      *(float4*)(C + (long long)m * ldc + n) = v;
    }
  }
}

// ---------------- prep: padded splits / transposes (validated) --------------
__global__ void k_prep() {
  int t = blockIdx.x * blockDim.x + threadIdx.x;
  const int NPAD = BATCH * L * HP;  // 41280
  if (t < NPAD) {
    int row = t / HP, i = t % HP;
    g_tailP[t] = (i < H) ? g_hidden[(long long)row * (4 * H) + 2 * H + i] : 1.f;
    return;
  }
  t -= NPAD;
  if (t < NPAD) {
    int row = t / HP, n = t % HP;
    g_xheadP[t] = (n < H) ? g_scoring[(long long)row * (2 * H) + n] : 1.f;
    return;
  }
  t -= NPAD;
  if (t < NPAD) {  // inPT[b][j][z]
    int b = t / (HP * L), rem = t % (HP * L);
    int j = rem / L, z = rem % L;
    g_inPT[t] = (j < H)
        ? g_hidden[(long long)(b * L + z) * (4 * H) + 3 * H + j] : 1.f;
    return;
  }
  t -= NPAD;
  if (t < NPAD) {  // xtailPT[b][m][y]
    int b = t / (HP * L), rem = t % (HP * L);
    int m = rem / L, y = rem % L;
    g_xtailPT[t] = (m < H)
        ? g_scoring[(long long)(b * L + y) * (2 * H) + H + m] : 1.f;
  }
}

// ---------------- softmax over last dim (160) (validated) -------------------
__global__ void k_softmax(float* __restrict__ lg, int nrows) {
  int w = (blockIdx.x * blockDim.x + threadIdx.x) >> 5;
  int lane = threadIdx.x & 31;
  if (w >= nrows) return;
  float* row = lg + (long long)w * L;
  float v[5];
  float mx = -1e30f;
#pragma unroll
  for (int t = 0; t < 5; ++t) {
    v[t] = row[t * 32 + lane];
    mx = fmaxf(mx, v[t]);
  }
#pragma unroll
  for (int o = 16; o; o >>= 1) mx = fmaxf(mx, __shfl_xor_sync(0xffffffffu, mx, o));
  float s = 0.f;
#pragma unroll
  for (int t = 0; t < 5; ++t) { v[t] = __expf(v[t] - mx); s += v[t]; }
#pragma unroll
  for (int o = 16; o; o >>= 1) s += __shfl_xor_sync(0xffffffffu, s, o);
  float inv = 1.f / s;
#pragma unroll
  for (int t = 0; t < 5; ++t) row[t * 32 + lane] = v[t] * inv;
}

// ---------------- Gt2[b][xq][y] -> Gt3[b][y][xq] (tiled transpose) ----------
__global__ void k_transpose(const float* __restrict__ in,
                            float* __restrict__ outp) {
  __shared__ float t[32][33];
  int b = blockIdx.z;
  int xq0 = blockIdx.x * 32, y0 = blockIdx.y * 32;
  const float* ip = in + (long long)b * (L * H) * L;
  float* op = outp + (long long)b * L * (L * H);
  int tx = threadIdx.x, ty0 = threadIdx.y;  // 32 x 8
  for (int i = ty0; i < 32; i += 8)
    t[i][tx] = ip[(long long)(xq0 + i) * L + (y0 + tx)];
  __syncthreads();
  for (int i = ty0; i < 32; i += 8)
    op[(long long)(y0 + i) * (L * H) + (xq0 + tx)] = t[tx][i];
}

// ---- score[b,r,x,y] = sum_q SP[(b,r,y,x)][q] * Gt3[b][y][x*128+q] ----------
__global__ void k_score(const float* __restrict__ SP,
                        const float* __restrict__ Gt3,
                        float* __restrict__ out) {
  long long w = ((long long)blockIdx.x * blockDim.x + threadIdx.x) >> 5;
  int lane = threadIdx.x & 31;
  if (w >= (long long)BATCH * R * L * L) return;
  int x = (int)(w % L);
  long long t = w / L;
  int y = (int)(t % L); t /= L;
  int r = (int)(t % R);
  int b = (int)(t / R);
  const float4* sp = (const float4*)(SP +
      ((long long)((b * R + r) * L + y) * L + x) * H);
  const float4* gt = (const float4*)(Gt3 +
      ((long long)(b * L + y) * L + x) * H);
  float4 a = sp[lane], g = gt[lane];
  float s = a.x * g.x + a.y * g.y + a.z * g.z + a.w * g.w;
#pragma unroll
  for (int o = 16; o; o >>= 1) s += __shfl_xor_sync(0xffffffffu, s, o);
  if (lane == 0) out[((long long)((b * R + r) * L + x)) * L + y] = s;
}

// ------------------------------- launch --------------------------------------
static const float* pick_by_size(void* const* d_in, const int* in_sizes,
                                 int n_in, int want, int fallback_idx) {
  for (int i = 0; i < n_in; ++i)
    if (in_sizes[i] == want) return (const float*)d_in[i];
  return (const float*)d_in[fallback_idx];
}

extern "C" void kernel_launch(void* const* d_in, const int* in_sizes, int n_in,
                              void* d_out, int out_size) {
  (void)out_size;
  const float* x      = pick_by_size(d_in, in_sizes, n_in, BATCH * L * D, 0);
  const float* Wspan  = pick_by_size(d_in, in_sizes, n_in, D * 4 * H, 1);
  const float* bspan  = pick_by_size(d_in, in_sizes, n_in, 4 * H, 2);
  const float* Wscore = pick_by_size(d_in, in_sizes, n_in, D * 2 * H, 3);
  const float* bscore = pick_by_size(d_in, in_sizes, n_in, 2 * H, 4);
  const float* Wtri   = pick_by_size(d_in, in_sizes, n_in, R * HP * H * HP, 5);
  const float* Wmlp   = pick_by_size(d_in, in_sizes, n_in, H * H, 6);
  const float* bmlp   = pick_by_size(d_in, in_sizes, n_in, H, 7);
  const float* Wfin   = pick_by_size(d_in, in_sizes, n_in, HP * H * HP, 8);
  float* out = (float*)d_out;

  float* d_hidden;  cudaGetSymbolAddress((void**)&d_hidden, g_hidden);
  float* d_scoring; cudaGetSymbolAddress((void**)&d_scoring, g_scoring);
  float* d_tailP;   cudaGetSymbolAddress((void**)&d_tailP, g_tailP);
  float* d_xheadP;  cudaGetSymbolAddress((void**)&d_xheadP, g_xheadP);
  float* d_inPT;    cudaGetSymbolAddress((void**)&d_inPT, g_inPT);
  float* d_xtailPT; cudaGetSymbolAddress((void**)&d_xtailPT, g_xtailPT);
  float* d_U;       cudaGetSymbolAddress((void**)&d_U, g_U);
  float* d_G;       cudaGetSymbolAddress((void**)&d_G, g_G);
  float* d_Gt2;     cudaGetSymbolAddress((void**)&d_Gt2, g_Gt2);
  float* d_Gt3;     cudaGetSymbolAddress((void**)&d_Gt3, g_Gt3);
  float* d_arena;   cudaGetSymbolAddress((void**)&d_arena, g_arena);
  float* d_W2 = d_arena + OFF_V;   // [b][(r,y)][k][z]  (13,107,200 per b)
  float* d_LG = d_arena + OFF_LG;  // [b][(r,y)][x][z]
  float* d_S  = d_arena + OFF_V;   // reuses W2 region (dead by then)
  float* d_SP = d_arena + OFF_LG;  // reuses LG region (dead by then)

  // 1) hidden = leaky(x @ Wspan + bspan)   [320,512], K=768
  gemm_t<80, 128><<<dim3(4, 4, 1), 160>>>(
      x, Wspan, d_hidden, 320, 512, 768, 768, 512, 512, 0, 0, 0, 1, bspan);
  // 2) scoring = leaky(x @ Wscore + bscore) [320,256], K=768
  gemm_t<80, 128><<<dim3(2, 4, 1), 160>>>(
      x, Wscore, d_scoring, 320, 256, 768, 768, 256, 256, 0, 0, 0, 1, bscore);
  // 3) padded splits / transposes
  k_prep<<<(4 * BATCH * L * HP + 255) / 256, 256>>>();
  // 4) U[(b,r)][y][k*129+j] = tailP[b] @ Wtri[r]; z = r
  for (int b = 0; b < BATCH; ++b)
    gemm_t<80, 128><<<dim3(129, 2, 4), 160>>>(
        d_tailP + (long long)b * L * HP, Wtri,
        d_U + (long long)b * R * L * NKJ,
        L, NKJ, HP, HP, NKJ, NKJ, 0, WTRI_R, (long long)L * NKJ, 0, nullptr);
  // 5) G[b][x][q*129+m] = xheadP[b] @ Wfin; z = b
  gemm_t<80, 128><<<dim3(129, 2, 2), 160>>>(
      d_xheadP, Wfin, d_G, L, NKJ, HP, HP, NKJ, NKJ,
      (long long)L * HP, 0, (long long)L * NKJ, 0, nullptr);
  // 6) Gt2[b][xq][y] = G[b] (as [20480,129]) @ xtailPT[b] [129,160]; z = b
  gemm_t<80, 160><<<dim3(1, 256, 2), 200>>>(
      d_G, d_xtailPT, d_Gt2, L * H, L, HP, HP, L, L,
      (long long)L * NKJ, (long long)HP * L, (long long)(L * H) * L, 0, nullptr);
  // 6b) Gt3[b][y][xq] = transpose(Gt2)
  k_transpose<<<dim3(640, 5, 2), dim3(32, 8)>>>(d_Gt2, d_Gt3);
  // 7) W2[b,(r,y)][k][z] = U[(b,r,y)] [128,129] @ inPT[b] [129,160]; z=(r,y)
  for (int b = 0; b < BATCH; ++b)
    gemm_t<64, 160><<<dim3(1, 2, R * L), 160>>>(
        d_U + (long long)b * R * L * NKJ, d_inPT + (long long)b * HP * L,
        d_W2 + (long long)b * W2_B,
        H, L, HP, HP, L, L, NKJ, 0, (long long)H * L, 0, nullptr);
  // 8) logits[b,(r,y)][x][z] = head[b] [160,128] @ W2[b,(r,y)] [128,160]
  for (int b = 0; b < BATCH; ++b)
    gemm_t<80, 160><<<dim3(1, 2, R * L), 200>>>(
        d_hidden + (long long)b * L * (4 * H) + H, d_W2 + (long long)b * W2_B,
        d_LG + (long long)b * LG_B,
        L, L, H, 4 * H, L, L, 0, (long long)H * L, (long long)L * L, 0, nullptr);
  // 9) softmax over z (in place)
  {
    int nrows = BATCH * R * L * L;
    k_softmax<<<(nrows * 32 + 255) / 256, 256>>>(d_LG, nrows);
  }
  // 10) S[b,(r,y)][x][h] = alpha [160,160] @ HinRepr[b] [160,128]
  for (int b = 0; b < BATCH; ++b)
    gemm_t<80, 128><<<dim3(1, 2, R * L), 160>>>(
        d_LG + (long long)b * LG_B, d_hidden + (long long)b * L * (4 * H),
        d_S + (long long)b * S_B,
        L, H, L, L, 4 * H, H, (long long)L * L, 0, (long long)L * H, 0, nullptr);
  // 11) SP = leaky(S @ Wmlp + bmlp)  [204800,128], K=128
  gemm_t<80, 128><<<dim3(1, 2560, 1), 160>>>(
      d_S, Wmlp, d_SP, BATCH * R * L * L, H, H, H, H, H, 0, 0, 0, 1, bmlp);
  // 12) score (coalesced)
  {
    long long nwarps = (long long)BATCH * R * L * L;
    k_score<<<(int)((nwarps * 32 + 255) / 256), 256>>>(d_SP, d_Gt3, out);
  }
}

// round 6
// speedup vs baseline: 1.6787x; 1.4515x over previous
#include <cuda_runtime.h>

#define DINLINE __device__ __forceinline__

namespace {
constexpr int L = 160, H = 128, HP = 129, R = 4, BATCH = 2, D = 768;
constexpr int NKJ = H * HP;                              // 16512
constexpr long long WTRI_R = (long long)HP * NKJ;        // 2130048

constexpr long long V_SZ  = (long long)BATCH * R * L * L * HP;  // 26,419,200
constexpr long long LG_SZ = (long long)BATCH * R * L * L * L;   // 32,768,000
constexpr long long OFF_V  = 0;        // W2 lives here, later SP
constexpr long long OFF_LG = V_SZ;     // logits/alpha
constexpr long long ARENA_SZ = V_SZ + LG_SZ;
constexpr long long W2_B = (long long)R * L * H * L;     // per-b W2 floats
constexpr long long SP_B = (long long)R * L * L * H;     // per-b SP floats
constexpr long long LG_B = (long long)R * L * L * L;     // per-b logits floats
}

// ------------------------- static device scratch ----------------------------
__device__ float g_hidden[BATCH * L * 4 * H];    // [b*L+l][512]
__device__ float g_scoring[BATCH * L * 2 * H];   // [b*L+l][256]
__device__ float g_tailP[BATCH * L * HP];        // [b*L+y][i], i=128 -> 1
__device__ float g_xheadP[BATCH * L * HP];       // [b*L+x][n], n=128 -> 1
__device__ float g_inPT[BATCH * HP * L];         // [b][j][z], j=128 -> 1
__device__ float g_xtailPT[BATCH * HP * L];      // [b][m][y], m=128 -> 1
__device__ float g_U[(long long)BATCH * R * L * NKJ];   // [(b*R+r)*L+y][k*129+j]
__device__ float g_G[(long long)BATCH * L * NKJ];       // [b][x][q*129+m]
__device__ float g_Gt2[(long long)BATCH * L * H * L];   // [b][x*128+q][y]
__device__ float g_Gt3[(long long)BATCH * L * L * H];   // [b][y][x*128+q]
__device__ float g_HRW[BATCH * L * H];                  // [b][z][q] = HinRepr@Wmlp
__device__ float g_arena[ARENA_SZ];

DINLINE float leaky(float v) { return v >= 0.f ? v : 0.1f * v; }

// ---- double-buffered register-staged GEMM: C = A @ B, 8x8 microtile --------
// A[M,K] lda, B[K,N] ldb, C[M,N] ldc; batch strides sA,sB,sC over blockIdx.z.
// ep==1: C = leaky(acc + bias[n]). K-edge zero-padded via guards.
template <int BM, int BN>
__global__ void __launch_bounds__((BM / 8) * (BN / 8)) gemm2(
    const float* __restrict__ A, const float* __restrict__ B,
    float* __restrict__ C, int M, int N, int K, int lda, int ldb, int ldc,
    long long sA, long long sB, long long sC, int ep,
    const float* __restrict__ bias) {
  constexpr int NT = (BM / 8) * (BN / 8);
  constexpr int AST = BM + 4;
  constexpr int AR = (BM * 16 + NT - 1) / NT;   // scalar A elems / thread
  constexpr int BR = (BN * 4 + NT - 1) / NT;    // float4 B vecs / thread
  __shared__ float As[2][16][AST];  // transposed: As[s][k][m]
  __shared__ float Bs[2][16][BN];   // Bs[s][k][n]
  A += (long long)blockIdx.z * sA;
  B += (long long)blockIdx.z * sB;
  C += (long long)blockIdx.z * sC;
  const int tid = threadIdx.x;
  const int tx = tid % (BN / 8), ty = tid / (BN / 8);
  const int m0 = blockIdx.y * BM, n0 = blockIdx.x * BN;

  float a_reg[AR];
  float4 b_reg[BR];

  auto load_regs = [&](int k0) {
#pragma unroll
    for (int t = 0; t < AR; ++t) {
      int idx = tid + t * NT;
      int m = idx >> 4, k = idx & 15;
      a_reg[t] = 0.f;
      if (idx < BM * 16 && k0 + k < K && m0 + m < M)
        a_reg[t] = A[(long long)(m0 + m) * lda + k0 + k];
    }
#pragma unroll
    for (int t = 0; t < BR; ++t) {
      int idx = tid + t * NT;
      int k = idx / (BN / 4), n4 = idx % (BN / 4);
      b_reg[t] = make_float4(0.f, 0.f, 0.f, 0.f);
      if (idx < BN * 4 && k0 + k < K)
        b_reg[t] = *(const float4*)(B + (long long)(k0 + k) * ldb + n0 + n4 * 4);
    }
  };
  auto store_smem = [&](int s) {
#pragma unroll
    for (int t = 0; t < AR; ++t) {
      int idx = tid + t * NT;
      if (idx < BM * 16) {
        int m = idx >> 4, k = idx & 15;
        As[s][k][m] = a_reg[t];
      }
    }
#pragma unroll
    for (int t = 0; t < BR; ++t) {
      int idx = tid + t * NT;
      if (idx < BN * 4) {
        int k = idx / (BN / 4), n4 = idx % (BN / 4);
        *(float4*)(&Bs[s][k][n4 * 4]) = b_reg[t];
      }
    }
  };

  float acc[8][8] = {};
  load_regs(0);
  store_smem(0);
  __syncthreads();
  int buf = 0;
  for (int k0 = 0; k0 < K; k0 += 16) {
    const bool next = (k0 + 16) < K;
    if (next) load_regs(k0 + 16);  // LDGs in flight during compute below
#pragma unroll
    for (int k = 0; k < 16; ++k) {
      float4 A0 = *(const float4*)(&As[buf][k][ty * 4]);
      float4 A1 = *(const float4*)(&As[buf][k][BM / 2 + ty * 4]);
      float4 B0 = *(const float4*)(&Bs[buf][k][tx * 4]);
      float4 B1 = *(const float4*)(&Bs[buf][k][BN / 2 + tx * 4]);
      float av[8] = {A0.x, A0.y, A0.z, A0.w, A1.x, A1.y, A1.z, A1.w};
      float bv[8] = {B0.x, B0.y, B0.z, B0.w, B1.x, B1.y, B1.z, B1.w};
#pragma unroll
      for (int i = 0; i < 8; ++i)
#pragma unroll
        for (int j = 0; j < 8; ++j)
          acc[i][j] = fmaf(av[i], bv[j], acc[i][j]);
    }
    if (next) store_smem(buf ^ 1);  // other buffer: safe, fenced by prior sync
    __syncthreads();
    buf ^= 1;
  }
  // epilogue
#pragma unroll
  for (int i = 0; i < 8; ++i) {
    int m = m0 + (i < 4 ? ty * 4 + i : BM / 2 + ty * 4 + (i - 4));
    if (m >= M) continue;
#pragma unroll
    for (int jh = 0; jh < 2; ++jh) {
      int n = n0 + (jh ? BN / 2 : 0) + tx * 4;
      if (n >= N) continue;
      float4 v = make_float4(acc[i][jh * 4 + 0], acc[i][jh * 4 + 1],
                             acc[i][jh * 4 + 2], acc[i][jh * 4 + 3]);
      if (ep == 1) {
        v.x = leaky(v.x + bias[n + 0]);
        v.y = leaky(v.y + bias[n + 1]);
        v.z = leaky(v.z + bias[n + 2]);
        v.w = leaky(v.w + bias[n + 3]);
      }
      *(float4*)(C + (long long)m * ldc + n) = v;
    }
  }
}

// ---------------- prep: padded splits / transposes (validated) --------------
__global__ void k_prep() {
  int t = blockIdx.x * blockDim.x + threadIdx.x;
  const int NPAD = BATCH * L * HP;  // 41280
  if (t < NPAD) {
    int row = t / HP, i = t % HP;
    g_tailP[t] = (i < H) ? g_hidden[(long long)row * (4 * H) + 2 * H + i] : 1.f;
    return;
  }
  t -= NPAD;
  if (t < NPAD) {
    int row = t / HP, n = t % HP;
    g_xheadP[t] = (n < H) ? g_scoring[(long long)row * (2 * H) + n] : 1.f;
    return;
  }
  t -= NPAD;
  if (t < NPAD) {  // inPT[b][j][z]
    int b = t / (HP * L), rem = t % (HP * L);
    int j = rem / L, z = rem % L;
    g_inPT[t] = (j < H)
        ? g_hidden[(long long)(b * L + z) * (4 * H) + 3 * H + j] : 1.f;
    return;
  }
  t -= NPAD;
  if (t < NPAD) {  // xtailPT[b][m][y]
    int b = t / (HP * L), rem = t % (HP * L);
    int m = rem / L, y = rem % L;
    g_xtailPT[t] = (m < H)
        ? g_scoring[(long long)(b * L + y) * (2 * H) + H + m] : 1.f;
  }
}

// ---------------- softmax over last dim (160) (validated) -------------------
__global__ void k_softmax(float* __restrict__ lg, int nrows) {
  int w = (blockIdx.x * blockDim.x + threadIdx.x) >> 5;
  int lane = threadIdx.x & 31;
  if (w >= nrows) return;
  float* row = lg + (long long)w * L;
  float v[5];
  float mx = -1e30f;
#pragma unroll
  for (int t = 0; t < 5; ++t) {
    v[t] = row[t * 32 + lane];
    mx = fmaxf(mx, v[t]);
  }
#pragma unroll
  for (int o = 16; o; o >>= 1) mx = fmaxf(mx, __shfl_xor_sync(0xffffffffu, mx, o));
  float s = 0.f;
#pragma unroll
  for (int t = 0; t < 5; ++t) { v[t] = __expf(v[t] - mx); s += v[t]; }
#pragma unroll
  for (int o = 16; o; o >>= 1) s += __shfl_xor_sync(0xffffffffu, s, o);
  float inv = 1.f / s;
#pragma unroll
  for (int t = 0; t < 5; ++t) row[t * 32 + lane] = v[t] * inv;
}

// ---------------- Gt2[b][xq][y] -> Gt3[b][y][xq] (tiled transpose) ----------
__global__ void k_transpose(const float* __restrict__ in,
                            float* __restrict__ outp) {
  __shared__ float t[32][33];
  int b = blockIdx.z;
  int xq0 = blockIdx.x * 32, y0 = blockIdx.y * 32;
  const float* ip = in + (long long)b * (L * H) * L;
  float* op = outp + (long long)b * L * (L * H);
  int tx = threadIdx.x, ty0 = threadIdx.y;  // 32 x 8
  for (int i = ty0; i < 32; i += 8)
    t[i][tx] = ip[(long long)(xq0 + i) * L + (y0 + tx)];
  __syncthreads();
  for (int i = ty0; i < 32; i += 8)
    op[(long long)(y0 + i) * (L * H) + (xq0 + tx)] = t[tx][i];
}

// ---- score[b,r,x,y] = sum_q SP[(b,r,y,x)][q] * Gt3[b][y][x*128+q] ----------
__global__ void k_score(const float* __restrict__ SP,
                        const float* __restrict__ Gt3,
                        float* __restrict__ out) {
  long long w = ((long long)blockIdx.x * blockDim.x + threadIdx.x) >> 5;
  int lane = threadIdx.x & 31;
  if (w >= (long long)BATCH * R * L * L) return;
  int x = (int)(w % L);
  long long t = w / L;
  int y = (int)(t % L); t /= L;
  int r = (int)(t % R);
  int b = (int)(t / R);
  const float4* sp = (const float4*)(SP +
      ((long long)((b * R + r) * L + y) * L + x) * H);
  const float4* gt = (const float4*)(Gt3 +
      ((long long)(b * L + y) * L + x) * H);
  float4 a = sp[lane], g = gt[lane];
  float s = a.x * g.x + a.y * g.y + a.z * g.z + a.w * g.w;
#pragma unroll
  for (int o = 16; o; o >>= 1) s += __shfl_xor_sync(0xffffffffu, s, o);
  if (lane == 0) out[((long long)((b * R + r) * L + x)) * L + y] = s;
}

// ------------------------------- launch --------------------------------------
static const float* pick_by_size(void* const* d_in, const int* in_sizes,
                                 int n_in, int want, int fallback_idx) {
  for (int i = 0; i < n_in; ++i)
    if (in_sizes[i] == want) return (const float*)d_in[i];
  return (const float*)d_in[fallback_idx];
}

extern "C" void kernel_launch(void* const* d_in, const int* in_sizes, int n_in,
                              void* d_out, int out_size) {
  (void)out_size;
  const float* x      = pick_by_size(d_in, in_sizes, n_in, BATCH * L * D, 0);
  const float* Wspan  = pick_by_size(d_in, in_sizes, n_in, D * 4 * H, 1);
  const float* bspan  = pick_by_size(d_in, in_sizes, n_in, 4 * H, 2);
  const float* Wscore = pick_by_size(d_in, in_sizes, n_in, D * 2 * H, 3);
  const float* bscore = pick_by_size(d_in, in_sizes, n_in, 2 * H, 4);
  const float* Wtri   = pick_by_size(d_in, in_sizes, n_in, R * HP * H * HP, 5);
  const float* Wmlp   = pick_by_size(d_in, in_sizes, n_in, H * H, 6);
  const float* bmlp   = pick_by_size(d_in, in_sizes, n_in, H, 7);
  const float* Wfin   = pick_by_size(d_in, in_sizes, n_in, HP * H * HP, 8);
  float* out = (float*)d_out;

  float* d_hidden;  cudaGetSymbolAddress((void**)&d_hidden, g_hidden);
  float* d_scoring; cudaGetSymbolAddress((void**)&d_scoring, g_scoring);
  float* d_tailP;   cudaGetSymbolAddress((void**)&d_tailP, g_tailP);
  float* d_xheadP;  cudaGetSymbolAddress((void**)&d_xheadP, g_xheadP);
  float* d_inPT;    cudaGetSymbolAddress((void**)&d_inPT, g_inPT);
  float* d_xtailPT; cudaGetSymbolAddress((void**)&d_xtailPT, g_xtailPT);
  float* d_U;       cudaGetSymbolAddress((void**)&d_U, g_U);
  float* d_G;       cudaGetSymbolAddress((void**)&d_G, g_G);
  float* d_Gt2;     cudaGetSymbolAddress((void**)&d_Gt2, g_Gt2);
  float* d_Gt3;     cudaGetSymbolAddress((void**)&d_Gt3, g_Gt3);
  float* d_HRW;     cudaGetSymbolAddress((void**)&d_HRW, g_HRW);
  float* d_arena;   cudaGetSymbolAddress((void**)&d_arena, g_arena);
  float* d_W2 = d_arena + OFF_V;   // [b][(r,y)][k][z]
  float* d_LG = d_arena + OFF_LG;  // [b][(r,y)][x][z]
  float* d_SP = d_arena + OFF_V;   // reuses W2 region (dead after logits)

  // 1) hidden = leaky(x @ Wspan + bspan)   [320,512], K=768
  gemm2<160, 128><<<dim3(4, 2, 1), 320>>>(
      x, Wspan, d_hidden, 320, 512, 768, 768, 512, 512, 0, 0, 0, 1, bspan);
  // 2) scoring = leaky(x @ Wscore + bscore) [320,256], K=768
  gemm2<160, 128><<<dim3(2, 2, 1), 320>>>(
      x, Wscore, d_scoring, 320, 256, 768, 768, 256, 256, 0, 0, 0, 1, bscore);
  // 3) padded splits / transposes
  k_prep<<<(4 * BATCH * L * HP + 255) / 256, 256>>>();
  // 4) U[(b,r)][y][k*129+j] = tailP[b] @ Wtri[r]; z = r
  for (int b = 0; b < BATCH; ++b)
    gemm2<160, 128><<<dim3(129, 1, 4), 320>>>(
        d_tailP + (long long)b * L * HP, Wtri,
        d_U + (long long)b * R * L * NKJ,
        L, NKJ, HP, HP, NKJ, NKJ, 0, WTRI_R, (long long)L * NKJ, 0, nullptr);
  // 5) G[b][x][q*129+m] = xheadP[b] @ Wfin; z = b
  gemm2<160, 128><<<dim3(129, 1, 2), 320>>>(
      d_xheadP, Wfin, d_G, L, NKJ, HP, HP, NKJ, NKJ,
      (long long)L * HP, 0, (long long)L * NKJ, 0, nullptr);
  // 6) Gt2[b][xq][y] = G[b] (as [20480,129]) @ xtailPT[b] [129,160]; z = b
  gemm2<128, 160><<<dim3(1, 160, 2), 320>>>(
      d_G, d_xtailPT, d_Gt2, L * H, L, HP, HP, L, L,
      (long long)L * NKJ, (long long)HP * L, (long long)(L * H) * L, 0, nullptr);
  // 6b) Gt3[b][y][xq] = transpose(Gt2)
  k_transpose<<<dim3(640, 5, 2), dim3(32, 8)>>>(d_Gt2, d_Gt3);
  // 7) W2[b,(r,y)][k][z] = U[(b,r,y)] [128,129] @ inPT[b] [129,160]; z=(r,y)
  for (int b = 0; b < BATCH; ++b)
    gemm2<128, 160><<<dim3(1, 1, R * L), 320>>>(
        d_U + (long long)b * R * L * NKJ, d_inPT + (long long)b * HP * L,
        d_W2 + (long long)b * W2_B,
        H, L, HP, HP, L, L, NKJ, 0, (long long)H * L, 0, nullptr);
  // 8) logits[b,(r,y)][x][z] = head[b] [160,128] @ W2[b,(r,y)] [128,160]
  for (int b = 0; b < BATCH; ++b)
    gemm2<160, 160><<<dim3(1, 1, R * L), 400>>>(
        d_hidden + (long long)b * L * (4 * H) + H, d_W2 + (long long)b * W2_B,
        d_LG + (long long)b * LG_B,
        L, L, H, 4 * H, L, L, 0, (long long)H * L, (long long)L * L, 0, nullptr);
  // 9) softmax over z (in place)
  {
    int nrows = BATCH * R * L * L;
    k_softmax<<<(nrows * 32 + 255) / 256, 256>>>(d_LG, nrows);
  }
  // 10) HRW[b] = HinRepr[b] [160,128] @ Wmlp [128,128]; z = b
  gemm2<160, 128><<<dim3(1, 1, 2), 320>>>(
      d_hidden, Wmlp, d_HRW, L, H, H, 4 * H, H, H,
      (long long)L * (4 * H), 0, (long long)L * H, 0, nullptr);
  // 11) SP[b,(r,y)][x][q] = leaky(alpha [160,160] @ HRW[b] [160,128] + bmlp)
  for (int b = 0; b < BATCH; ++b)
    gemm2<160, 128><<<dim3(1, 1, R * L), 320>>>(
        d_LG + (long long)b * LG_B, d_HRW + (long long)b * L * H,
        d_SP + (long long)b * SP_B,
        L, H, L, L, H, H, (long long)L * L, 0, (long long)L * H, 1, bmlp);
  // 12) score (coalesced)
  {
    long long nwarps = (long long)BATCH * R * L * L;
    k_score<<<(int)((nwarps * 32 + 255) / 256), 256>>>(d_SP, d_Gt3, out);
  }
}

// round 9
// speedup vs baseline: 1.7470x; 1.0406x over previous
#include <cuda_runtime.h>

#define DINLINE __device__ __forceinline__

namespace {
constexpr int L = 160, H = 128, HP = 129, R = 4, BATCH = 2, D = 768;
constexpr int NKJ = H * HP;                              // 16512
constexpr long long WTRI_R = (long long)HP * NKJ;        // 2130048

constexpr long long V_SZ  = (long long)BATCH * R * L * L * HP;  // 26,419,200
constexpr long long LG_SZ = (long long)BATCH * R * L * L * L;   // 32,768,000
constexpr long long OFF_V  = 0;        // W2 lives here, later SP
constexpr long long OFF_LG = V_SZ;     // logits/alpha
constexpr long long ARENA_SZ = V_SZ + LG_SZ;
constexpr long long W2_B = (long long)R * L * H * L;     // per-b W2 floats
constexpr long long SP_B = (long long)R * L * L * H;     // per-b SP floats
constexpr long long LG_B = (long long)R * L * L * L;     // per-b logits floats
}

// ------------------------- static device scratch ----------------------------
__device__ float g_hidden[BATCH * L * 4 * H];    // [b*L+l][512]
__device__ float g_scoring[BATCH * L * 2 * H];   // [b*L+l][256]
__device__ float g_tailP[BATCH * L * HP];        // [b*L+y][i], i=128 -> 1
__device__ float g_xheadP[BATCH * L * HP];       // [b*L+x][n], n=128 -> 1
__device__ float g_inPT[BATCH * HP * L];         // [b][j][z], j=128 -> 1
__device__ float g_xtailPT[BATCH * HP * L];      // [b][m][y], m=128 -> 1
__device__ float g_U[(long long)BATCH * R * L * NKJ];   // [(b*R+r)*L+y][k*129+j]
__device__ float g_G[(long long)BATCH * L * NKJ];       // [b][x][q*129+m]
__device__ float g_Gt2[(long long)BATCH * L * H * L];   // [b][x*128+q][y]
__device__ float g_Gt3[(long long)BATCH * L * L * H];   // [b][y][x*128+q]
__device__ float g_HRW[BATCH * L * H];                  // [b][z][q] = HinRepr@Wmlp
__device__ float g_arena[ARENA_SZ];

DINLINE float leaky(float v) { return v >= 0.f ? v : 0.1f * v; }

// ---- double-buffered register-staged GEMM: C = A @ B, 8x8 microtile --------
// A[M,K] lda, B[K,N] ldb, C[M,N] ldc; batch strides sA,sB,sC over blockIdx.z.
// REQUIRES: M % BM == 0 and N % BN == 0 for every launch (all launches below
// are exact; guards removed). KG=true compiles K-edge zero-fill guards
// (needed only for K=129); KG=false requires K % 16 == 0.
// ep==1: C = leaky(acc + bias[n]).
template <int BM, int BN, bool KG>
__global__ void __launch_bounds__((BM / 8) * (BN / 8)) gemm3(
    const float* __restrict__ A, const float* __restrict__ B,
    float* __restrict__ C, int M, int N, int K, int lda, int ldb, int ldc,
    long long sA, long long sB, long long sC, int ep,
    const float* __restrict__ bias) {
  constexpr int NT = (BM / 8) * (BN / 8);
  constexpr int AST = BM + 4;
  constexpr int AR = (BM * 16 + NT - 1) / NT;   // scalar A elems / thread
  constexpr int BR = (BN * 4 + NT - 1) / NT;    // float4 B vecs / thread
  __shared__ float As[2][16][AST];  // transposed: As[s][k][m]
  __shared__ float Bs[2][16][BN];   // Bs[s][k][n]
  A += (long long)blockIdx.z * sA;
  B += (long long)blockIdx.z * sB;
  C += (long long)blockIdx.z * sC;
  const int tid = threadIdx.x;
  const int tx = tid % (BN / 8), ty = tid / (BN / 8);
  const int m0 = blockIdx.y * BM, n0 = blockIdx.x * BN;

  float a_reg[AR];
  float4 b_reg[BR];

  auto load_regs = [&](int k0) {
#pragma unroll
    for (int t = 0; t < AR; ++t) {
      int idx = tid + t * NT;
      if (idx < BM * 16) {
        int m = idx >> 4, k = idx & 15;
        if (KG) {
          a_reg[t] = 0.f;
          if (k0 + k < K) a_reg[t] = A[(long long)(m0 + m) * lda + k0 + k];
        } else {
          a_reg[t] = A[(long long)(m0 + m) * lda + k0 + k];
        }
      }
    }
#pragma unroll
    for (int t = 0; t < BR; ++t) {
      int idx = tid + t * NT;
      if (idx < BN * 4) {
        int k = idx / (BN / 4), n4 = idx % (BN / 4);
        if (KG) {
          b_reg[t] = make_float4(0.f, 0.f, 0.f, 0.f);
          if (k0 + k < K)
            b_reg[t] =
                *(const float4*)(B + (long long)(k0 + k) * ldb + n0 + n4 * 4);
        } else {
          b_reg[t] =
              *(const float4*)(B + (long long)(k0 + k) * ldb + n0 + n4 * 4);
        }
      }
    }
  };
  auto store_smem = [&](int s) {
#pragma unroll
    for (int t = 0; t < AR; ++t) {
      int idx = tid + t * NT;
      if (idx < BM * 16) {
        int m = idx >> 4, k = idx & 15;
        As[s][k][m] = a_reg[t];
      }
    }
#pragma unroll
    for (int t = 0; t < BR; ++t) {
      int idx = tid + t * NT;
      if (idx < BN * 4) {
        int k = idx / (BN / 4), n4 = idx % (BN / 4);
        *(float4*)(&Bs[s][k][n4 * 4]) = b_reg[t];
      }
    }
  };

  float acc[8][8] = {};
  load_regs(0);
  store_smem(0);
  __syncthreads();
  int buf = 0;
  for (int k0 = 0; k0 < K; k0 += 16) {
    const bool next = (k0 + 16) < K;
    if (next) load_regs(k0 + 16);  // LDGs in flight during compute below
#pragma unroll
    for (int k = 0; k < 16; ++k) {
      float4 A0 = *(const float4*)(&As[buf][k][ty * 4]);
      float4 A1 = *(const float4*)(&As[buf][k][BM / 2 + ty * 4]);
      float4 B0 = *(const float4*)(&Bs[buf][k][tx * 4]);
      float4 B1 = *(const float4*)(&Bs[buf][k][BN / 2 + tx * 4]);
      float av[8] = {A0.x, A0.y, A0.z, A0.w, A1.x, A1.y, A1.z, A1.w};
      float bv[8] = {B0.x, B0.y, B0.z, B0.w, B1.x, B1.y, B1.z, B1.w};
#pragma unroll
      for (int i = 0; i < 8; ++i)
#pragma unroll
        for (int j = 0; j < 8; ++j)
          acc[i][j] = fmaf(av[i], bv[j], acc[i][j]);
    }
    if (next) store_smem(buf ^ 1);  // other buffer: safe, fenced by prior sync
    __syncthreads();
    buf ^= 1;
  }
  // epilogue (no M/N guards — launches are tile-exact)
#pragma unroll
  for (int i = 0; i < 8; ++i) {
    int m = m0 + (i < 4 ? ty * 4 + i : BM / 2 + ty * 4 + (i - 4));
#pragma unroll
    for (int jh = 0; jh < 2; ++jh) {
      int n = n0 + (jh ? BN / 2 : 0) + tx * 4;
      float4 v = make_float4(acc[i][jh * 4 + 0], acc[i][jh * 4 + 1],
                             acc[i][jh * 4 + 2], acc[i][jh * 4 + 3]);
      if (ep == 1) {
        v.x = leaky(v.x + bias[n + 0]);
        v.y = leaky(v.y + bias[n + 1]);
        v.z = leaky(v.z + bias[n + 2]);
        v.w = leaky(v.w + bias[n + 3]);
      }
      *(float4*)(C + (long long)m * ldc + n) = v;
    }
  }
}

// ---------------- prep: padded splits / transposes (validated) --------------
__global__ void k_prep() {
  int t = blockIdx.x * blockDim.x + threadIdx.x;
  const int NPAD = BATCH * L * HP;  // 41280
  if (t < NPAD) {
    int row = t / HP, i = t % HP;
    g_tailP[t] = (i < H) ? g_hidden[(long long)row * (4 * H) + 2 * H + i] : 1.f;
    return;
  }
  t -= NPAD;
  if (t < NPAD) {
    int row = t / HP, n = t % HP;
    g_xheadP[t] = (n < H) ? g_scoring[(long long)row * (2 * H) + n] : 1.f;
    return;
  }
  t -= NPAD;
  if (t < NPAD) {  // inPT[b][j][z]
    int b = t / (HP * L), rem = t % (HP * L);
    int j = rem / L, z = rem % L;
    g_inPT[t] = (j < H)
        ? g_hidden[(long long)(b * L + z) * (4 * H) + 3 * H + j] : 1.f;
    return;
  }
  t -= NPAD;
  if (t < NPAD) {  // xtailPT[b][m][y]
    int b = t / (HP * L), rem = t % (HP * L);
    int m = rem / L, y = rem % L;
    g_xtailPT[t] = (m < H)
        ? g_scoring[(long long)(b * L + y) * (2 * H) + H + m] : 1.f;
  }
}

// ---------------- softmax over last dim (160) (validated) -------------------
__global__ void k_softmax(float* __restrict__ lg, int nrows) {
  int w = (blockIdx.x * blockDim.x + threadIdx.x) >> 5;
  int lane = threadIdx.x & 31;
  if (w >= nrows) return;
  float* row = lg + (long long)w * L;
  float v[5];
  float mx = -1e30f;
#pragma unroll
  for (int t = 0; t < 5; ++t) {
    v[t] = row[t * 32 + lane];
    mx = fmaxf(mx, v[t]);
  }
#pragma unroll
  for (int o = 16; o; o >>= 1) mx = fmaxf(mx, __shfl_xor_sync(0xffffffffu, mx, o));
  float s = 0.f;
#pragma unroll
  for (int t = 0; t < 5; ++t) { v[t] = __expf(v[t] - mx); s += v[t]; }
#pragma unroll
  for (int o = 16; o; o >>= 1) s += __shfl_xor_sync(0xffffffffu, s, o);
  float inv = 1.f / s;
#pragma unroll
  for (int t = 0; t < 5; ++t) row[t * 32 + lane] = v[t] * inv;
}

// ---------------- Gt2[b][xq][y] -> Gt3[b][y][xq] (tiled transpose) ----------
__global__ void k_transpose(const float* __restrict__ in,
                            float* __restrict__ outp) {
  __shared__ float t[32][33];
  int b = blockIdx.z;
  int xq0 = blockIdx.x * 32, y0 = blockIdx.y * 32;
  const float* ip = in + (long long)b * (L * H) * L;
  float* op = outp + (long long)b * L * (L * H);
  int tx = threadIdx.x, ty0 = threadIdx.y;  // 32 x 8
  for (int i = ty0; i < 32; i += 8)
    t[i][tx] = ip[(long long)(xq0 + i) * L + (y0 + tx)];
  __syncthreads();
  for (int i = ty0; i < 32; i += 8)
    op[(long long)(y0 + i) * (L * H) + (xq0 + tx)] = t[tx][i];
}

// ---- score[b,r,x,y] = sum_q SP[(b,r,y,x)][q] * Gt3[b][y][x*128+q] ----------
__global__ void k_score(const float* __restrict__ SP,
                        const float* __restrict__ Gt3,
                        float* __restrict__ out) {
  long long w = ((long long)blockIdx.x * blockDim.x + threadIdx.x) >> 5;
  int lane = threadIdx.x & 31;
  if (w >= (long long)BATCH * R * L * L) return;
  int x = (int)(w % L);
  long long t = w / L;
  int y = (int)(t % L); t /= L;
  int r = (int)(t % R);
  int b = (int)(t / R);
  const float4* sp = (const float4*)(SP +
      ((long long)((b * R + r) * L + y) * L + x) * H);
  const float4* gt = (const float4*)(Gt3 +
      ((long long)(b * L + y) * L + x) * H);
  float4 a = sp[lane], g = gt[lane];
  float s = a.x * g.x + a.y * g.y + a.z * g.z + a.w * g.w;
#pragma unroll
  for (int o = 16; o; o >>= 1) s += __shfl_xor_sync(0xffffffffu, s, o);
  if (lane == 0) out[((long long)((b * R + r) * L + x)) * L + y] = s;
}

// ------------------------------- launch --------------------------------------
static const float* pick_by_size(void* const* d_in, const int* in_sizes,
                                 int n_in, int want, int fallback_idx) {
  for (int i = 0; i < n_in; ++i)
    if (in_sizes[i] == want) return (const float*)d_in[i];
  return (const float*)d_in[fallback_idx];
}

extern "C" void kernel_launch(void* const* d_in, const int* in_sizes, int n_in,
                              void* d_out, int out_size) {
  (void)out_size;
  const float* x      = pick_by_size(d_in, in_sizes, n_in, BATCH * L * D, 0);
  const float* Wspan  = pick_by_size(d_in, in_sizes, n_in, D * 4 * H, 1);
  const float* bspan  = pick_by_size(d_in, in_sizes, n_in, 4 * H, 2);
  const float* Wscore = pick_by_size(d_in, in_sizes, n_in, D * 2 * H, 3);
  const float* bscore = pick_by_size(d_in, in_sizes, n_in, 2 * H, 4);
  const float* Wtri   = pick_by_size(d_in, in_sizes, n_in, R * HP * H * HP, 5);
  const float* Wmlp   = pick_by_size(d_in, in_sizes, n_in, H * H, 6);
  const float* bmlp   = pick_by_size(d_in, in_sizes, n_in, H, 7);
  const float* Wfin   = pick_by_size(d_in, in_sizes, n_in, HP * H * HP, 8);
  float* out = (float*)d_out;

  float* d_hidden;  cudaGetSymbolAddress((void**)&d_hidden, g_hidden);
  float* d_scoring; cudaGetSymbolAddress((void**)&d_scoring, g_scoring);
  float* d_tailP;   cudaGetSymbolAddress((void**)&d_tailP, g_tailP);
  float* d_xheadP;  cudaGetSymbolAddress((void**)&d_xheadP, g_xheadP);
  float* d_inPT;    cudaGetSymbolAddress((void**)&d_inPT, g_inPT);
  float* d_xtailPT; cudaGetSymbolAddress((void**)&d_xtailPT, g_xtailPT);
  float* d_U;       cudaGetSymbolAddress((void**)&d_U, g_U);
  float* d_G;       cudaGetSymbolAddress((void**)&d_G, g_G);
  float* d_Gt2;     cudaGetSymbolAddress((void**)&d_Gt2, g_Gt2);
  float* d_Gt3;     cudaGetSymbolAddress((void**)&d_Gt3, g_Gt3);
  float* d_HRW;     cudaGetSymbolAddress((void**)&d_HRW, g_HRW);
  float* d_arena;   cudaGetSymbolAddress((void**)&d_arena, g_arena);
  float* d_W2 = d_arena + OFF_V;   // [b][(r,y)][k][z]
  float* d_LG = d_arena + OFF_LG;  // [b][(r,y)][x][z]
  float* d_SP = d_arena + OFF_V;   // reuses W2 region (dead after logits)

  // 1) hidden = leaky(x @ Wspan + bspan)   [320,512], K=768 (exact tiles)
  gemm3<160, 128, false><<<dim3(4, 2, 1), 320>>>(
      x, Wspan, d_hidden, 320, 512, 768, 768, 512, 512, 0, 0, 0, 1, bspan);
  // 2) scoring = leaky(x @ Wscore + bscore) [320,256], K=768
  gemm3<160, 128, false><<<dim3(2, 2, 1), 320>>>(
      x, Wscore, d_scoring, 320, 256, 768, 768, 256, 256, 0, 0, 0, 1, bscore);
  // 3) padded splits / transposes
  k_prep<<<(4 * BATCH * L * HP + 255) / 256, 256>>>();
  // 4) U[(b,r)][y][k*129+j] = tailP[b] @ Wtri[r]; z = r  (K=129 -> KG)
  for (int b = 0; b < BATCH; ++b)
    gemm3<160, 128, true><<<dim3(129, 1, 4), 320>>>(
        d_tailP + (long long)b * L * HP, Wtri,
        d_U + (long long)b * R * L * NKJ,
        L, NKJ, HP, HP, NKJ, NKJ, 0, WTRI_R, (long long)L * NKJ, 0, nullptr);
  // 5) G[b][x][q*129+m] = xheadP[b] @ Wfin; z = b  (K=129 -> KG)
  gemm3<160, 128, true><<<dim3(129, 1, 2), 320>>>(
      d_xheadP, Wfin, d_G, L, NKJ, HP, HP, NKJ, NKJ,
      (long long)L * HP, 0, (long long)L * NKJ, 0, nullptr);
  // 6) Gt2[b][xq][y] = G[b] (as [20480,129]) @ xtailPT[b] [129,160]; (K=129)
  gemm3<128, 160, true><<<dim3(1, 160, 2), 320>>>(
      d_G, d_xtailPT, d_Gt2, L * H, L, HP, HP, L, L,
      (long long)L * NKJ, (long long)HP * L, (long long)(L * H) * L, 0, nullptr);
  // 6b) Gt3[b][y][xq] = transpose(Gt2)
  k_transpose<<<dim3(640, 5, 2), dim3(32, 8)>>>(d_Gt2, d_Gt3);
  // 7) W2[b,(r,y)][k][z] = U[(b,r,y)] [128,129] @ inPT[b] [129,160]  (K=129)
  for (int b = 0; b < BATCH; ++b)
    gemm3<128, 160, true><<<dim3(1, 1, R * L), 320>>>(
        d_U + (long long)b * R * L * NKJ, d_inPT + (long long)b * HP * L,
        d_W2 + (long long)b * W2_B,
        H, L, HP, HP, L, L, NKJ, 0, (long long)H * L, 0, nullptr);
  // 8) logits[b,(r,y)][x][z] = head[b] [160,128] @ W2[b,(r,y)] [128,160]
  for (int b = 0; b < BATCH; ++b)
    gemm3<160, 160, false><<<dim3(1, 1, R * L), 400>>>(
        d_hidden + (long long)b * L * (4 * H) + H, d_W2 + (long long)b * W2_B,
        d_LG + (long long)b * LG_B,
        L, L, H, 4 * H, L, L, 0, (long long)H * L, (long long)L * L, 0, nullptr);
  // 9) softmax over z (in place)
  {
    int nrows = BATCH * R * L * L;
    k_softmax<<<(nrows * 32 + 255) / 256, 256>>>(d_LG, nrows);
  }
  // 10) HRW[b] = HinRepr[b] [160,128] @ Wmlp [128,128]; z = b  (K=128)
  gemm3<160, 128, false><<<dim3(1, 1, 2), 320>>>(
      d_hidden, Wmlp, d_HRW, L, H, H, 4 * H, H, H,
      (long long)L * (4 * H), 0, (long long)L * H, 0, nullptr);
  // 11) SP[b,(r,y)][x][q] = leaky(alpha [160,160] @ HRW[b] [160,128] + bmlp)
  for (int b = 0; b < BATCH; ++b)
    gemm3<160, 128, false><<<dim3(1, 1, R * L), 320>>>(
        d_LG + (long long)b * LG_B, d_HRW + (long long)b * L * H,
        d_SP + (long long)b * SP_B,
        L, H, L, L, H, H, (long long)L * L, 0, (long long)L * H, 1, bmlp);
  // 12) score (coalesced)
  {
    long long nwarps = (long long)BATCH * R * L * L;
    k_score<<<(int)((nwarps * 32 + 255) / 256), 256>>>(d_SP, d_Gt3, out);
  }
}

// round 10
// speedup vs baseline: 2.0282x; 1.1610x over previous
#include <cuda_runtime.h>
#include <cstdint>

#define DINLINE __device__ __forceinline__

namespace {
constexpr int L = 160, H = 128, HP = 129, R = 4, BATCH = 2, D = 768;
constexpr int NKJ = H * HP;                              // 16512
constexpr long long WTRI_R = (long long)HP * NKJ;        // 2130048

constexpr long long V_SZ  = (long long)BATCH * R * L * L * HP;  // 26,419,200
constexpr long long LG_SZ = (long long)BATCH * R * L * L * L;   // 32,768,000
constexpr long long OFF_V  = 0;        // W2 lives here, later SP
constexpr long long OFF_LG = V_SZ;     // logits/alpha
constexpr long long ARENA_SZ = V_SZ + LG_SZ;
constexpr long long W2_B = (long long)R * L * H * L;     // per-b W2 floats
constexpr long long SP_B = (long long)R * L * L * H;     // per-b SP floats
constexpr long long LG_B = (long long)R * L * L * L;     // per-b logits floats
}

// ------------------------- static device scratch ----------------------------
__device__ float g_hidden[BATCH * L * 4 * H];    // [b*L+l][512]
__device__ float g_scoring[BATCH * L * 2 * H];   // [b*L+l][256]
__device__ float g_tailP[BATCH * L * HP];        // [b*L+y][i], i=128 -> 1
__device__ float g_xheadP[BATCH * L * HP];       // [b*L+x][n], n=128 -> 1
__device__ float g_inPT[BATCH * HP * L];         // [b][j][z], j=128 -> 1
__device__ float g_xtailPT[BATCH * HP * L];      // [b][m][y], m=128 -> 1
__device__ float g_U[(long long)BATCH * R * L * NKJ];   // [(b*R+r)*L+y][k*129+j]
__device__ float g_G[(long long)BATCH * L * NKJ];       // [b][x][q*129+m]
__device__ float g_Gt2[(long long)BATCH * L * H * L];   // [b][x*128+q][y]
__device__ float g_Gt3[(long long)BATCH * L * L * H];   // [b][y][x*128+q]
__device__ float g_HRW[BATCH * L * H];                  // [b][z][q] = HinRepr@Wmlp
__device__ float g_arena[ARENA_SZ];

DINLINE float leaky(float v) { return v >= 0.f ? v : 0.1f * v; }

// ---- cp.async helpers ------------------------------------------------------
DINLINE void cp4(uint32_t dst, const float* src, int src_bytes) {
  asm volatile("cp.async.ca.shared.global [%0], [%1], 4, %2;"
               :: "r"(dst), "l"(src), "r"(src_bytes));
}
DINLINE void cp16(uint32_t dst, const float* src, int src_bytes) {
  asm volatile("cp.async.cg.shared.global [%0], [%1], 16, %2;"
               :: "r"(dst), "l"(src), "r"(src_bytes));
}
#define CP_COMMIT() asm volatile("cp.async.commit_group;" ::: "memory")
#define CP_WAIT0()  asm volatile("cp.async.wait_group 0;" ::: "memory")

// ---- cp.async double-buffered GEMM: C = A @ B, 8x8 microtile ----------------
// A[M,K] lda, B[K,N] ldb, C[M,N] ldc; batch strides sA,sB,sC over blockIdx.z.
// REQUIRES M % BM == 0 and N % BN == 0 (all launches are tile-exact).
// KG=true: K-edge zero-fill (K=129); KG=false requires K % 16 == 0.
// OCC: min blocks/SM hint (2 for 320-thread configs -> reg cap 102).
// ep==1: C = leaky(acc + bias[n]).
template <int BM, int BN, bool KG, int OCC>
__global__ void __launch_bounds__((BM / 8) * (BN / 8), OCC) gemm4(
    const float* __restrict__ A, const float* __restrict__ B,
    float* __restrict__ C, int M, int N, int K, int lda, int ldb, int ldc,
    long long sA, long long sB, long long sC, int ep,
    const float* __restrict__ bias) {
  constexpr int NT = (BM / 8) * (BN / 8);
  constexpr int AST = BM + 4;
  constexpr int AR = (BM * 16 + NT - 1) / NT;   // scalar A elems / thread
  constexpr int BR = (BN * 4 + NT - 1) / NT;    // float4 B vecs / thread
  __shared__ float As[2][16][AST];  // transposed: As[s][k][m]
  __shared__ float Bs[2][16][BN];   // Bs[s][k][n]
  A += (long long)blockIdx.z * sA;
  B += (long long)blockIdx.z * sB;
  C += (long long)blockIdx.z * sC;
  const int tid = threadIdx.x;
  const int tx = tid % (BN / 8), ty = tid / (BN / 8);
  const int m0 = blockIdx.y * BM, n0 = blockIdx.x * BN;

  const uint32_t sbA = (uint32_t)__cvta_generic_to_shared(&As[0][0][0]);
  const uint32_t sbB = (uint32_t)__cvta_generic_to_shared(&Bs[0][0][0]);

  auto prefetch = [&](int k0, int s) {
#pragma unroll
    for (int t = 0; t < AR; ++t) {
      int idx = tid + t * NT;
      if (idx < BM * 16) {
        int m = idx >> 4, k = idx & 15;
        int vb = 4, kk = k0 + k;
        if (KG) {
          if (kk >= K) { vb = 0; kk = K - 1; }
        }
        cp4(sbA + (((s * 16 + k) * AST + m) << 2),
            A + (long long)(m0 + m) * lda + kk, vb);
      }
    }
#pragma unroll
    for (int t = 0; t < BR; ++t) {
      int idx = tid + t * NT;
      if (idx < BN * 4) {
        int k = idx / (BN / 4), n4 = idx % (BN / 4);
        int vb = 16, kk = k0 + k;
        if (KG) {
          if (kk >= K) { vb = 0; kk = K - 1; }
        }
        cp16(sbB + (((s * 16 + k) * BN + n4 * 4) << 2),
             B + (long long)kk * ldb + n0 + n4 * 4, vb);
      }
    }
  };

  float acc[8][8] = {};
  prefetch(0, 0);
  CP_COMMIT();
  int buf = 0;
  for (int k0 = 0; k0 < K; k0 += 16) {
    CP_WAIT0();
    __syncthreads();  // buf data visible; all warps past previous compute
    const bool next = (k0 + 16) < K;
    if (next) {        // safe: sync above followed everyone's compute of buf^1
      prefetch(k0 + 16, buf ^ 1);
      CP_COMMIT();
    }
#pragma unroll
    for (int k = 0; k < 16; ++k) {
      float4 A0 = *(const float4*)(&As[buf][k][ty * 4]);
      float4 A1 = *(const float4*)(&As[buf][k][BM / 2 + ty * 4]);
      float4 B0 = *(const float4*)(&Bs[buf][k][tx * 4]);
      float4 B1 = *(const float4*)(&Bs[buf][k][BN / 2 + tx * 4]);
      float av[8] = {A0.x, A0.y, A0.z, A0.w, A1.x, A1.y, A1.z, A1.w};
      float bv[8] = {B0.x, B0.y, B0.z, B0.w, B1.x, B1.y, B1.z, B1.w};
#pragma unroll
      for (int i = 0; i < 8; ++i)
#pragma unroll
        for (int j = 0; j < 8; ++j)
          acc[i][j] = fmaf(av[i], bv[j], acc[i][j]);
    }
    buf ^= 1;
  }
  // epilogue (no M/N guards — launches are tile-exact)
#pragma unroll
  for (int i = 0; i < 8; ++i) {
    int m = m0 + (i < 4 ? ty * 4 + i : BM / 2 + ty * 4 + (i - 4));
#pragma unroll
    for (int jh = 0; jh < 2; ++jh) {
      int n = n0 + (jh ? BN / 2 : 0) + tx * 4;
      float4 v = make_float4(acc[i][jh * 4 + 0], acc[i][jh * 4 + 1],
                             acc[i][jh * 4 + 2], acc[i][jh * 4 + 3]);
      if (ep == 1) {
        v.x = leaky(v.x + bias[n + 0]);
        v.y = leaky(v.y + bias[n + 1]);
        v.z = leaky(v.z + bias[n + 2]);
        v.w = leaky(v.w + bias[n + 3]);
      }
      *(float4*)(C + (long long)m * ldc + n) = v;
    }
  }
}

// ---------------- prep: padded splits / transposes (validated) --------------
__global__ void k_prep() {
  int t = blockIdx.x * blockDim.x + threadIdx.x;
  const int NPAD = BATCH * L * HP;  // 41280
  if (t < NPAD) {
    int row = t / HP, i = t % HP;
    g_tailP[t] = (i < H) ? g_hidden[(long long)row * (4 * H) + 2 * H + i] : 1.f;
    return;
  }
  t -= NPAD;
  if (t < NPAD) {
    int row = t / HP, n = t % HP;
    g_xheadP[t] = (n < H) ? g_scoring[(long long)row * (2 * H) + n] : 1.f;
    return;
  }
  t -= NPAD;
  if (t < NPAD) {  // inPT[b][j][z]
    int b = t / (HP * L), rem = t % (HP * L);
    int j = rem / L, z = rem % L;
    g_inPT[t] = (j < H)
        ? g_hidden[(long long)(b * L + z) * (4 * H) + 3 * H + j] : 1.f;
    return;
  }
  t -= NPAD;
  if (t < NPAD) {  // xtailPT[b][m][y]
    int b = t / (HP * L), rem = t % (HP * L);
    int m = rem / L, y = rem % L;
    g_xtailPT[t] = (m < H)
        ? g_scoring[(long long)(b * L + y) * (2 * H) + H + m] : 1.f;
  }
}

// ---------------- softmax over last dim (160) (validated) -------------------
__global__ void k_softmax(float* __restrict__ lg, int nrows) {
  int w = (blockIdx.x * blockDim.x + threadIdx.x) >> 5;
  int lane = threadIdx.x & 31;
  if (w >= nrows) return;
  float* row = lg + (long long)w * L;
  float v[5];
  float mx = -1e30f;
#pragma unroll
  for (int t = 0; t < 5; ++t) {
    v[t] = row[t * 32 + lane];
    mx = fmaxf(mx, v[t]);
  }
#pragma unroll
  for (int o = 16; o; o >>= 1) mx = fmaxf(mx, __shfl_xor_sync(0xffffffffu, mx, o));
  float s = 0.f;
#pragma unroll
  for (int t = 0; t < 5; ++t) { v[t] = __expf(v[t] - mx); s += v[t]; }
#pragma unroll
  for (int o = 16; o; o >>= 1) s += __shfl_xor_sync(0xffffffffu, s, o);
  float inv = 1.f / s;
#pragma unroll
  for (int t = 0; t < 5; ++t) row[t * 32 + lane] = v[t] * inv;
}

// ---------------- Gt2[b][xq][y] -> Gt3[b][y][xq] (tiled transpose) ----------
__global__ void k_transpose(const float* __restrict__ in,
                            float* __restrict__ outp) {
  __shared__ float t[32][33];
  int b = blockIdx.z;
  int xq0 = blockIdx.x * 32, y0 = blockIdx.y * 32;
  const float* ip = in + (long long)b * (L * H) * L;
  float* op = outp + (long long)b * L * (L * H);
  int tx = threadIdx.x, ty0 = threadIdx.y;  // 32 x 8
  for (int i = ty0; i < 32; i += 8)
    t[i][tx] = ip[(long long)(xq0 + i) * L + (y0 + tx)];
  __syncthreads();
  for (int i = ty0; i < 32; i += 8)
    op[(long long)(y0 + i) * (L * H) + (xq0 + tx)] = t[tx][i];
}

// ---- score[b,r,x,y] = sum_q SP[(b,r,y,x)][q] * Gt3[b][y][x*128+q] ----------
__global__ void k_score(const float* __restrict__ SP,
                        const float* __restrict__ Gt3,
                        float* __restrict__ out) {
  long long w = ((long long)blockIdx.x * blockDim.x + threadIdx.x) >> 5;
  int lane = threadIdx.x & 31;
  if (w >= (long long)BATCH * R * L * L) return;
  int x = (int)(w % L);
  long long t = w / L;
  int y = (int)(t % L); t /= L;
  int r = (int)(t % R);
  int b = (int)(t / R);
  const float4* sp = (const float4*)(SP +
      ((long long)((b * R + r) * L + y) * L + x) * H);
  const float4* gt = (const float4*)(Gt3 +
      ((long long)(b * L + y) * L + x) * H);
  float4 a = sp[lane], g = gt[lane];
  float s = a.x * g.x + a.y * g.y + a.z * g.z + a.w * g.w;
#pragma unroll
  for (int o = 16; o; o >>= 1) s += __shfl_xor_sync(0xffffffffu, s, o);
  if (lane == 0) out[((long long)((b * R + r) * L + x)) * L + y] = s;
}

// ------------------------------- launch --------------------------------------
static const float* pick_by_size(void* const* d_in, const int* in_sizes,
                                 int n_in, int want, int fallback_idx) {
  for (int i = 0; i < n_in; ++i)
    if (in_sizes[i] == want) return (const float*)d_in[i];
  return (const float*)d_in[fallback_idx];
}

extern "C" void kernel_launch(void* const* d_in, const int* in_sizes, int n_in,
                              void* d_out, int out_size) {
  (void)out_size;
  const float* x      = pick_by_size(d_in, in_sizes, n_in, BATCH * L * D, 0);
  const float* Wspan  = pick_by_size(d_in, in_sizes, n_in, D * 4 * H, 1);
  const float* bspan  = pick_by_size(d_in, in_sizes, n_in, 4 * H, 2);
  const float* Wscore = pick_by_size(d_in, in_sizes, n_in, D * 2 * H, 3);
  const float* bscore = pick_by_size(d_in, in_sizes, n_in, 2 * H, 4);
  const float* Wtri   = pick_by_size(d_in, in_sizes, n_in, R * HP * H * HP, 5);
  const float* Wmlp   = pick_by_size(d_in, in_sizes, n_in, H * H, 6);
  const float* bmlp   = pick_by_size(d_in, in_sizes, n_in, H, 7);
  const float* Wfin   = pick_by_size(d_in, in_sizes, n_in, HP * H * HP, 8);
  float* out = (float*)d_out;

  float* d_hidden;  cudaGetSymbolAddress((void**)&d_hidden, g_hidden);
  float* d_scoring; cudaGetSymbolAddress((void**)&d_scoring, g_scoring);
  float* d_tailP;   cudaGetSymbolAddress((void**)&d_tailP, g_tailP);
  float* d_xheadP;  cudaGetSymbolAddress((void**)&d_xheadP, g_xheadP);
  float* d_inPT;    cudaGetSymbolAddress((void**)&d_inPT, g_inPT);
  float* d_xtailPT; cudaGetSymbolAddress((void**)&d_xtailPT, g_xtailPT);
  float* d_U;       cudaGetSymbolAddress((void**)&d_U, g_U);
  float* d_G;       cudaGetSymbolAddress((void**)&d_G, g_G);
  float* d_Gt2;     cudaGetSymbolAddress((void**)&d_Gt2, g_Gt2);
  float* d_Gt3;     cudaGetSymbolAddress((void**)&d_Gt3, g_Gt3);
  float* d_HRW;     cudaGetSymbolAddress((void**)&d_HRW, g_HRW);
  float* d_arena;   cudaGetSymbolAddress((void**)&d_arena, g_arena);
  float* d_W2 = d_arena + OFF_V;   // [b][(r,y)][k][z]
  float* d_LG = d_arena + OFF_LG;  // [b][(r,y)][x][z]
  float* d_SP = d_arena + OFF_V;   // reuses W2 region (dead after logits)

  // 1) hidden = leaky(x @ Wspan + bspan)   [320,512], K=768 (exact tiles)
  gemm4<160, 128, false, 2><<<dim3(4, 2, 1), 320>>>(
      x, Wspan, d_hidden, 320, 512, 768, 768, 512, 512, 0, 0, 0, 1, bspan);
  // 2) scoring = leaky(x @ Wscore + bscore) [320,256], K=768
  gemm4<160, 128, false, 2><<<dim3(2, 2, 1), 320>>>(
      x, Wscore, d_scoring, 320, 256, 768, 768, 256, 256, 0, 0, 0, 1, bscore);
  // 3) padded splits / transposes
  k_prep<<<(4 * BATCH * L * HP + 255) / 256, 256>>>();
  // 4) U[(b,r)][y][k*129+j] = tailP[b] @ Wtri[r]; z = r  (K=129 -> KG)
  for (int b = 0; b < BATCH; ++b)
    gemm4<160, 128, true, 2><<<dim3(129, 1, 4), 320>>>(
        d_tailP + (long long)b * L * HP, Wtri,
        d_U + (long long)b * R * L * NKJ,
        L, NKJ, HP, HP, NKJ, NKJ, 0, WTRI_R, (long long)L * NKJ, 0, nullptr);
  // 5) G[b][x][q*129+m] = xheadP[b] @ Wfin; z = b  (K=129 -> KG)
  gemm4<160, 128, true, 2><<<dim3(129, 1, 2), 320>>>(
      d_xheadP, Wfin, d_G, L, NKJ, HP, HP, NKJ, NKJ,
      (long long)L * HP, 0, (long long)L * NKJ, 0, nullptr);
  // 6) Gt2[b][xq][y] = G[b] (as [20480,129]) @ xtailPT[b] [129,160]; (K=129)
  gemm4<128, 160, true, 2><<<dim3(1, 160, 2), 320>>>(
      d_G, d_xtailPT, d_Gt2, L * H, L, HP, HP, L, L,
      (long long)L * NKJ, (long long)HP * L, (long long)(L * H) * L, 0, nullptr);
  // 6b) Gt3[b][y][xq] = transpose(Gt2)
  k_transpose<<<dim3(640, 5, 2), dim3(32, 8)>>>(d_Gt2, d_Gt3);
  // 7) W2[b,(r,y)][k][z] = U[(b,r,y)] [128,129] @ inPT[b] [129,160]  (K=129)
  for (int b = 0; b < BATCH; ++b)
    gemm4<128, 160, true, 2><<<dim3(1, 1, R * L), 320>>>(
        d_U + (long long)b * R * L * NKJ, d_inPT + (long long)b * HP * L,
        d_W2 + (long long)b * W2_B,
        H, L, HP, HP, L, L, NKJ, 0, (long long)H * L, 0, nullptr);
  // 8) logits[b,(r,y)][x][z] = head[b] [160,128] @ W2[b,(r,y)] [128,160]
  for (int b = 0; b < BATCH; ++b)
    gemm4<160, 160, false, 1><<<dim3(1, 1, R * L), 400>>>(
        d_hidden + (long long)b * L * (4 * H) + H, d_W2 + (long long)b * W2_B,
        d_LG + (long long)b * LG_B,
        L, L, H, 4 * H, L, L, 0, (long long)H * L, (long long)L * L, 0, nullptr);
  // 9) softmax over z (in place)
  {
    int nrows = BATCH * R * L * L;
    k_softmax<<<(nrows * 32 + 255) / 256, 256>>>(d_LG, nrows);
  }
  // 10) HRW[b] = HinRepr[b] [160,128] @ Wmlp [128,128]; z = b  (K=128)
  gemm4<160, 128, false, 2><<<dim3(1, 1, 2), 320>>>(
      d_hidden, Wmlp, d_HRW, L, H, H, 4 * H, H, H,
      (long long)L * (4 * H), 0, (long long)L * H, 0, nullptr);
  // 11) SP[b,(r,y)][x][q] = leaky(alpha [160,160] @ HRW[b] [160,128] + bmlp)
  for (int b = 0; b < BATCH; ++b)
    gemm4<160, 128, false, 2><<<dim3(1, 1, R * L), 320>>>(
        d_LG + (long long)b * LG_B, d_HRW + (long long)b * L * H,
        d_SP + (long long)b * SP_B,
        L, H, L, L, H, H, (long long)L * L, 0, (long long)L * H, 1, bmlp);
  // 12) score (coalesced)
  {
    long long nwarps = (long long)BATCH * R * L * L;
    k_score<<<(int)((nwarps * 32 + 255) / 256), 256>>>(d_SP, d_Gt3, out);
  }
}

// round 11
// speedup vs baseline: 2.1402x; 1.0552x over previous
#include <cuda_runtime.h>
#include <cstdint>

#define DINLINE __device__ __forceinline__

namespace {
constexpr int L = 160, H = 128, HP = 129, R = 4, BATCH = 2, D = 768;
constexpr int NKJ = H * HP;                              // 16512
constexpr long long WTRI_R = (long long)HP * NKJ;        // 2130048

constexpr long long V_SZ  = (long long)BATCH * R * L * L * HP;  // 26,419,200
constexpr long long LG_SZ = (long long)BATCH * R * L * L * L;   // 32,768,000
constexpr long long OFF_V  = 0;        // W2 lives here, later SP
constexpr long long OFF_LG = V_SZ;     // logits/alpha
constexpr long long ARENA_SZ = V_SZ + LG_SZ;
constexpr long long W2_B = (long long)R * L * H * L;     // per-b W2 floats
constexpr long long SP_B = (long long)R * L * L * H;     // per-b SP floats
constexpr long long LG_B = (long long)R * L * L * L;     // per-b logits floats

constexpr int SM_160_128 = (2 * 32 * 164 + 2 * 32 * 128) * 4;  // 74752
constexpr int SM_128_160 = (2 * 32 * 132 + 2 * 32 * 160) * 4;  // 74752
constexpr int SM_160_160 = (2 * 32 * 164 + 2 * 32 * 160) * 4;  // 82944
}

// ------------------------- static device scratch ----------------------------
__device__ float g_hidden[BATCH * L * 4 * H];    // [b*L+l][512]
__device__ float g_scoring[BATCH * L * 2 * H];   // [b*L+l][256]
__device__ float g_inPT[BATCH * HP * L];         // [b][j][z], row j=128 -> 1
__device__ float g_xtailPT[BATCH * HP * L];      // [b][m][y], row m=128 -> 1
__device__ float g_U[(long long)BATCH * R * L * NKJ];   // [(b*R+r)*L+y][k*129+j]
__device__ float g_G[(long long)BATCH * L * NKJ];       // [b][x][q*129+m]
__device__ float g_Gt2[(long long)BATCH * L * H * L];   // [b][x*128+q][y]
__device__ float g_Gt3[(long long)BATCH * L * L * H];   // [b][y][x*128+q]
__device__ float g_HRW[BATCH * L * H];                  // [b][z][q] = HinRepr@Wmlp
__device__ float g_arena[ARENA_SZ];

DINLINE float leaky(float v) { return v >= 0.f ? v : 0.1f * v; }

// ---- cp.async helpers ------------------------------------------------------
DINLINE void cp4(uint32_t dst, const float* src) {
  asm volatile("cp.async.ca.shared.global [%0], [%1], 4;"
               :: "r"(dst), "l"(src));
}
DINLINE void cp16(uint32_t dst, const float* src) {
  asm volatile("cp.async.cg.shared.global [%0], [%1], 16;"
               :: "r"(dst), "l"(src));
}
#define CP_COMMIT() asm volatile("cp.async.commit_group;" ::: "memory")
#define CP_WAIT0()  asm volatile("cp.async.wait_group 0;" ::: "memory")

// ---- cp.async double-buffered GEMM, BK=32, 8x8 microtile, exact tiles -------
// A[M,K] lda, B[K,N] ldb, C[M,N] ldc; batch strides sA,sB,sC over blockIdx.z.
// REQUIRES: M % BM == 0, N % BN == 0, K % 32 == 0.
// ep: 0 = none
//     1 = leaky(acc + bias[n])            (bias param)
//     2 = acc + B[K][n]                   (folds a pad ROW of B; z-safe)
//     3 = acc + A[m][K]                   (folds a pad COL of A; z-safe)
template <int BM, int BN, int OCC>
__global__ void __launch_bounds__((BM / 8) * (BN / 8), OCC) gemm5(
    const float* __restrict__ A, const float* __restrict__ B,
    float* __restrict__ C, int M, int N, int K, int lda, int ldb, int ldc,
    long long sA, long long sB, long long sC, int ep,
    const float* __restrict__ bias) {
  constexpr int NT = (BM / 8) * (BN / 8);
  constexpr int AST = BM + 4;
  constexpr int AR = (BM * 32 + NT - 1) / NT;   // scalar A elems / thread
  constexpr int BR = (BN * 8 + NT - 1) / NT;    // float4 B vecs / thread
  extern __shared__ float smem[];
  float* As = smem;                 // [2][32][AST] transposed: As[s][k][m]
  float* Bs = smem + 2 * 32 * AST;  // [2][32][BN]
  A += (long long)blockIdx.z * sA;
  B += (long long)blockIdx.z * sB;
  C += (long long)blockIdx.z * sC;
  const int tid = threadIdx.x;
  const int tx = tid % (BN / 8), ty = tid / (BN / 8);
  const int m0 = blockIdx.y * BM, n0 = blockIdx.x * BN;

  const uint32_t sbA = (uint32_t)__cvta_generic_to_shared(As);
  const uint32_t sbB = (uint32_t)__cvta_generic_to_shared(Bs);

  auto prefetch = [&](int k0, int s) {
#pragma unroll
    for (int t = 0; t < AR; ++t) {
      int idx = tid + t * NT;
      if (idx < BM * 32) {
        int m = idx >> 5, k = idx & 31;
        cp4(sbA + (((s * 32 + k) * AST + m) << 2),
            A + (long long)(m0 + m) * lda + k0 + k);
      }
    }
#pragma unroll
    for (int t = 0; t < BR; ++t) {
      int idx = tid + t * NT;
      if (idx < BN * 8) {
        int k = idx / (BN / 4), n4 = idx % (BN / 4);
        cp16(sbB + (((s * 32 + k) * BN + n4 * 4) << 2),
             B + (long long)(k0 + k) * ldb + n0 + n4 * 4);
      }
    }
  };

  float acc[8][8] = {};
  prefetch(0, 0);
  CP_COMMIT();
  int buf = 0;
  for (int k0 = 0; k0 < K; k0 += 32) {
    CP_WAIT0();
    __syncthreads();  // buf data visible; all warps past previous compute
    const bool next = (k0 + 32) < K;
    if (next) {
      prefetch(k0 + 32, buf ^ 1);
      CP_COMMIT();
    }
    const float* Ab = As + buf * 32 * AST;
    const float* Bb = Bs + buf * 32 * BN;
#pragma unroll 16
    for (int k = 0; k < 32; ++k) {
      float4 A0 = *(const float4*)(Ab + k * AST + ty * 4);
      float4 A1 = *(const float4*)(Ab + k * AST + BM / 2 + ty * 4);
      float4 B0 = *(const float4*)(Bb + k * BN + tx * 4);
      float4 B1 = *(const float4*)(Bb + k * BN + BN / 2 + tx * 4);
      float av[8] = {A0.x, A0.y, A0.z, A0.w, A1.x, A1.y, A1.z, A1.w};
      float bv[8] = {B0.x, B0.y, B0.z, B0.w, B1.x, B1.y, B1.z, B1.w};
#pragma unroll
      for (int i = 0; i < 8; ++i)
#pragma unroll
        for (int j = 0; j < 8; ++j)
          acc[i][j] = fmaf(av[i], bv[j], acc[i][j]);
    }
    buf ^= 1;
  }
  // epilogue (no M/N guards — launches are tile-exact)
  float4 br0 = make_float4(0.f, 0.f, 0.f, 0.f), br1 = br0;
  if (ep == 2) {  // pad row of B
    const float* Brow = B + (long long)K * ldb;
    br0 = *(const float4*)(Brow + n0 + tx * 4);
    br1 = *(const float4*)(Brow + n0 + BN / 2 + tx * 4);
  }
#pragma unroll
  for (int i = 0; i < 8; ++i) {
    int m = m0 + (i < 4 ? ty * 4 + i : BM / 2 + ty * 4 + (i - 4));
    float ra = (ep == 3) ? A[(long long)m * lda + K] : 0.f;  // pad col of A
#pragma unroll
    for (int jh = 0; jh < 2; ++jh) {
      int n = n0 + (jh ? BN / 2 : 0) + tx * 4;
      float4 v = make_float4(acc[i][jh * 4 + 0], acc[i][jh * 4 + 1],
                             acc[i][jh * 4 + 2], acc[i][jh * 4 + 3]);
      if (ep == 1) {
        v.x = leaky(v.x + bias[n + 0]);
        v.y = leaky(v.y + bias[n + 1]);
        v.z = leaky(v.z + bias[n + 2]);
        v.w = leaky(v.w + bias[n + 3]);
      } else if (ep == 2) {
        float4 br = jh ? br1 : br0;
        v.x += br.x; v.y += br.y; v.z += br.z; v.w += br.w;
      } else if (ep == 3) {
        v.x += ra; v.y += ra; v.z += ra; v.w += ra;
      }
      *(float4*)(C + (long long)m * ldc + n) = v;
    }
  }
}

// ---------------- prep: inPT / xtailPT transposes only ----------------------
__global__ void k_prep2() {
  int t = blockIdx.x * blockDim.x + threadIdx.x;
  const int NPAD = BATCH * HP * L;  // 41280
  if (t < NPAD) {  // inPT[b][j][z]
    int b = t / (HP * L), rem = t % (HP * L);
    int j = rem / L, z = rem % L;
    g_inPT[t] = (j < H)
        ? g_hidden[(long long)(b * L + z) * (4 * H) + 3 * H + j] : 1.f;
    return;
  }
  t -= NPAD;
  if (t < NPAD) {  // xtailPT[b][m][y]
    int b = t / (HP * L), rem = t % (HP * L);
    int m = rem / L, y = rem % L;
    g_xtailPT[t] = (m < H)
        ? g_scoring[(long long)(b * L + y) * (2 * H) + H + m] : 1.f;
  }
}

// ---------------- softmax over last dim (160) (validated) -------------------
__global__ void k_softmax(float* __restrict__ lg, int nrows) {
  int w = (blockIdx.x * blockDim.x + threadIdx.x) >> 5;
  int lane = threadIdx.x & 31;
  if (w >= nrows) return;
  float* row = lg + (long long)w * L;
  float v[5];
  float mx = -1e30f;
#pragma unroll
  for (int t = 0; t < 5; ++t) {
    v[t] = row[t * 32 + lane];
    mx = fmaxf(mx, v[t]);
  }
#pragma unroll
  for (int o = 16; o; o >>= 1) mx = fmaxf(mx, __shfl_xor_sync(0xffffffffu, mx, o));
  float s = 0.f;
#pragma unroll
  for (int t = 0; t < 5; ++t) { v[t] = __expf(v[t] - mx); s += v[t]; }
#pragma unroll
  for (int o = 16; o; o >>= 1) s += __shfl_xor_sync(0xffffffffu, s, o);
  float inv = 1.f / s;
#pragma unroll
  for (int t = 0; t < 5; ++t) row[t * 32 + lane] = v[t] * inv;
}

// ---------------- Gt2[b][xq][y] -> Gt3[b][y][xq] (tiled transpose) ----------
__global__ void k_transpose(const float* __restrict__ in,
                            float* __restrict__ outp) {
  __shared__ float t[32][33];
  int b = blockIdx.z;
  int xq0 = blockIdx.x * 32, y0 = blockIdx.y * 32;
  const float* ip = in + (long long)b * (L * H) * L;
  float* op = outp + (long long)b * L * (L * H);
  int tx = threadIdx.x, ty0 = threadIdx.y;  // 32 x 8
  for (int i = ty0; i < 32; i += 8)
    t[i][tx] = ip[(long long)(xq0 + i) * L + (y0 + tx)];
  __syncthreads();
  for (int i = ty0; i < 32; i += 8)
    op[(long long)(y0 + i) * (L * H) + (xq0 + tx)] = t[tx][i];
}

// ---- score[b,r,x,y] = sum_q SP[(b,r,y,x)][q] * Gt3[b][y][x*128+q] ----------
__global__ void k_score(const float* __restrict__ SP,
                        const float* __restrict__ Gt3,
                        float* __restrict__ out) {
  long long w = ((long long)blockIdx.x * blockDim.x + threadIdx.x) >> 5;
  int lane = threadIdx.x & 31;
  if (w >= (long long)BATCH * R * L * L) return;
  int x = (int)(w % L);
  long long t = w / L;
  int y = (int)(t % L); t /= L;
  int r = (int)(t % R);
  int b = (int)(t / R);
  const float4* sp = (const float4*)(SP +
      ((long long)((b * R + r) * L + y) * L + x) * H);
  const float4* gt = (const float4*)(Gt3 +
      ((long long)(b * L + y) * L + x) * H);
  float4 a = sp[lane], g = gt[lane];
  float s = a.x * g.x + a.y * g.y + a.z * g.z + a.w * g.w;
#pragma unroll
  for (int o = 16; o; o >>= 1) s += __shfl_xor_sync(0xffffffffu, s, o);
  if (lane == 0) out[((long long)((b * R + r) * L + x)) * L + y] = s;
}

// ------------------------------- launch --------------------------------------
static const float* pick_by_size(void* const* d_in, const int* in_sizes,
                                 int n_in, int want, int fallback_idx) {
  for (int i = 0; i < n_in; ++i)
    if (in_sizes[i] == want) return (const float*)d_in[i];
  return (const float*)d_in[fallback_idx];
}

extern "C" void kernel_launch(void* const* d_in, const int* in_sizes, int n_in,
                              void* d_out, int out_size) {
  (void)out_size;
  const float* x      = pick_by_size(d_in, in_sizes, n_in, BATCH * L * D, 0);
  const float* Wspan  = pick_by_size(d_in, in_sizes, n_in, D * 4 * H, 1);
  const float* bspan  = pick_by_size(d_in, in_sizes, n_in, 4 * H, 2);
  const float* Wscore = pick_by_size(d_in, in_sizes, n_in, D * 2 * H, 3);
  const float* bscore = pick_by_size(d_in, in_sizes, n_in, 2 * H, 4);
  const float* Wtri   = pick_by_size(d_in, in_sizes, n_in, R * HP * H * HP, 5);
  const float* Wmlp   = pick_by_size(d_in, in_sizes, n_in, H * H, 6);
  const float* bmlp   = pick_by_size(d_in, in_sizes, n_in, H, 7);
  const float* Wfin   = pick_by_size(d_in, in_sizes, n_in, HP * H * HP, 8);
  float* out = (float*)d_out;

  float* d_hidden;  cudaGetSymbolAddress((void**)&d_hidden, g_hidden);
  float* d_scoring; cudaGetSymbolAddress((void**)&d_scoring, g_scoring);
  float* d_inPT;    cudaGetSymbolAddress((void**)&d_inPT, g_inPT);
  float* d_xtailPT; cudaGetSymbolAddress((void**)&d_xtailPT, g_xtailPT);
  float* d_U;       cudaGetSymbolAddress((void**)&d_U, g_U);
  float* d_G;       cudaGetSymbolAddress((void**)&d_G, g_G);
  float* d_Gt2;     cudaGetSymbolAddress((void**)&d_Gt2, g_Gt2);
  float* d_Gt3;     cudaGetSymbolAddress((void**)&d_Gt3, g_Gt3);
  float* d_HRW;     cudaGetSymbolAddress((void**)&d_HRW, g_HRW);
  float* d_arena;   cudaGetSymbolAddress((void**)&d_arena, g_arena);
  float* d_W2 = d_arena + OFF_V;   // [b][(r,y)][k][z]
  float* d_LG = d_arena + OFF_LG;  // [b][(r,y)][x][z]
  float* d_SP = d_arena + OFF_V;   // reuses W2 region (dead after logits)

  cudaFuncSetAttribute(gemm5<160, 128, 2>,
                       cudaFuncAttributeMaxDynamicSharedMemorySize, SM_160_128);
  cudaFuncSetAttribute(gemm5<128, 160, 2>,
                       cudaFuncAttributeMaxDynamicSharedMemorySize, SM_128_160);
  cudaFuncSetAttribute(gemm5<160, 160, 1>,
                       cudaFuncAttributeMaxDynamicSharedMemorySize, SM_160_160);

  // 1) hidden = leaky(x @ Wspan + bspan)   [320,512], K=768
  gemm5<160, 128, 2><<<dim3(4, 2, 1), 320, SM_160_128>>>(
      x, Wspan, d_hidden, 320, 512, 768, 768, 512, 512, 0, 0, 0, 1, bspan);
  // 2) scoring = leaky(x @ Wscore + bscore) [320,256], K=768
  gemm5<160, 128, 2><<<dim3(2, 2, 1), 320, SM_160_128>>>(
      x, Wscore, d_scoring, 320, 256, 768, 768, 256, 256, 0, 0, 0, 1, bscore);
  // 3) transposes for inPT / xtailPT
  k_prep2<<<(2 * BATCH * HP * L + 255) / 256, 256>>>();
  // 4) U[(b,r)][y][:] = h_tail[b] @ Wtri[r][0:128] + Wtri[r][128] (ep=2); z=r
  for (int b = 0; b < BATCH; ++b)
    gemm5<160, 128, 2><<<dim3(129, 1, 4), 320, SM_160_128>>>(
        d_hidden + (long long)b * L * (4 * H) + 2 * H, Wtri,
        d_U + (long long)b * R * L * NKJ,
        L, NKJ, H, 4 * H, NKJ, NKJ, 0, WTRI_R, (long long)L * NKJ, 2, nullptr);
  // 5) G[b][x][:] = x_head[b] @ Wfin[0:128] + Wfin[128] (ep=2); z = b
  gemm5<160, 128, 2><<<dim3(129, 1, 2), 320, SM_160_128>>>(
      d_scoring, Wfin, d_G, L, NKJ, H, 2 * H, NKJ, NKJ,
      (long long)L * (2 * H), 0, (long long)L * NKJ, 2, nullptr);
  // 6) Gt2[b][xq][y] = G[b][xq][0:128] @ xtailPT[b][0:128] + G[b][xq][128] (ep=3)
  gemm5<128, 160, 2><<<dim3(1, 160, 2), 320, SM_128_160>>>(
      d_G, d_xtailPT, d_Gt2, L * H, L, H, HP, L, L,
      (long long)L * NKJ, (long long)HP * L, (long long)(L * H) * L, 3, nullptr);
  // 6b) Gt3[b][y][xq] = transpose(Gt2)
  k_transpose<<<dim3(640, 5, 2), dim3(32, 8)>>>(d_Gt2, d_Gt3);
  // 7) W2[b,(r,y)][k][z] = U[k][0:128] @ inPT[b][0:128] + U[k][128] (ep=3)
  for (int b = 0; b < BATCH; ++b)
    gemm5<128, 160, 2><<<dim3(1, 1, R * L), 320, SM_128_160>>>(
        d_U + (long long)b * R * L * NKJ, d_inPT + (long long)b * HP * L,
        d_W2 + (long long)b * W2_B,
        H, L, H, HP, L, L, NKJ, 0, (long long)H * L, 3, nullptr);
  // 8) logits[b,(r,y)][x][z] = h_head[b] [160,128] @ W2 [128,160]
  for (int b = 0; b < BATCH; ++b)
    gemm5<160, 160, 1><<<dim3(1, 1, R * L), 400, SM_160_160>>>(
        d_hidden + (long long)b * L * (4 * H) + H, d_W2 + (long long)b * W2_B,
        d_LG + (long long)b * LG_B,
        L, L, H, 4 * H, L, L, 0, (long long)H * L, (long long)L * L, 0, nullptr);
  // 9) softmax over z (in place)
  {
    int nrows = BATCH * R * L * L;
    k_softmax<<<(nrows * 32 + 255) / 256, 256>>>(d_LG, nrows);
  }
  // 10) HRW[b] = h_in_repr[b] [160,128] @ Wmlp [128,128]; z = b
  gemm5<160, 128, 2><<<dim3(1, 1, 2), 320, SM_160_128>>>(
      d_hidden, Wmlp, d_HRW, L, H, H, 4 * H, H, H,
      (long long)L * (4 * H), 0, (long long)L * H, 0, nullptr);
  // 11) SP[b,(r,y)][x][q] = leaky(alpha [160,160] @ HRW[b] [160,128] + bmlp)
  for (int b = 0; b < BATCH; ++b)
    gemm5<160, 128, 2><<<dim3(1, 1, R * L), 320, SM_160_128>>>(
        d_LG + (long long)b * LG_B, d_HRW + (long long)b * L * H,
        d_SP + (long long)b * SP_B,
        L, H, L, L, H, H, (long long)L * L, 0, (long long)L * H, 1, bmlp);
  // 12) score (coalesced)
  {
    long long nwarps = (long long)BATCH * R * L * L;
    k_score<<<(int)((nwarps * 32 + 255) / 256), 256>>>(d_SP, d_Gt3, out);
  }
}

// round 12
// speedup vs baseline: 2.1568x; 1.0078x over previous
#include <cuda_runtime.h>
#include <cstdint>

#define DINLINE __device__ __forceinline__

namespace {
constexpr int L = 160, H = 128, HP = 129, R = 4, BATCH = 2, D = 768;
constexpr int NKJ = H * HP;                              // 16512
constexpr long long WTRI_R = (long long)HP * NKJ;        // 2130048

constexpr long long V_SZ  = (long long)BATCH * R * L * L * HP;  // 26,419,200
constexpr long long LG_SZ = (long long)BATCH * R * L * L * L;   // 32,768,000
constexpr long long OFF_V  = 0;        // W2
constexpr long long OFF_LG = V_SZ;     // logits/alpha
constexpr long long ARENA_SZ = V_SZ + LG_SZ;
constexpr long long W2_B = (long long)R * L * H * L;     // per-b W2 floats
constexpr long long LG_B = (long long)R * L * L * L;     // per-b logits floats

constexpr int SM_160_128 = (2 * 32 * 164 + 2 * 32 * 128) * 4;  // 74752
constexpr int SM_128_160 = (2 * 32 * 132 + 2 * 32 * 160) * 4;  // 74752
constexpr int SM_80_160  = (2 * 32 * 84  + 2 * 32 * 160) * 4;  // 62464
}

// ------------------------- static device scratch ----------------------------
__device__ float g_hidden[BATCH * L * 4 * H];    // [b*L+l][512]
__device__ float g_scoring[BATCH * L * 2 * H];   // [b*L+l][256]
__device__ float g_inPT[BATCH * HP * L];         // [b][j][z], row j=128 -> 1
__device__ float g_xtailPT[BATCH * HP * L];      // [b][m][y], row m=128 -> 1
__device__ float g_U[(long long)BATCH * R * L * NKJ];   // [(b*R+r)*L+y][k*129+j]
__device__ float g_G[(long long)BATCH * L * NKJ];       // [b][x][q*129+m]
__device__ float g_Gt2[(long long)BATCH * L * H * L];   // [b][x*128+q][y]
__device__ float g_Gt3[(long long)BATCH * L * L * H];   // [b][y][x*128+q]
__device__ float g_HRW[BATCH * L * H];                  // [b][z][q] = HinRepr@Wmlp
__device__ float g_arena[ARENA_SZ];

DINLINE float leaky(float v) { return v >= 0.f ? v : 0.1f * v; }

// ---- cp.async helpers ------------------------------------------------------
DINLINE void cp4(uint32_t dst, const float* src) {
  asm volatile("cp.async.ca.shared.global [%0], [%1], 4;"
               :: "r"(dst), "l"(src));
}
DINLINE void cp16(uint32_t dst, const float* src) {
  asm volatile("cp.async.cg.shared.global [%0], [%1], 16;"
               :: "r"(dst), "l"(src));
}
#define CP_COMMIT() asm volatile("cp.async.commit_group;" ::: "memory")
#define CP_WAIT0()  asm volatile("cp.async.wait_group 0;" ::: "memory")

// ---- cp.async double-buffered GEMM, BK=32, 8x8 microtile, exact tiles -------
// Batched over blockIdx.z with split index: bz = z / ZD, rz = z % ZD.
//   A += bz*sA + rz*sA2;  B += bz*sB + rz*sB2;  C += z*sC.
// REQUIRES: M % BM == 0, N % BN == 0, K % 32 == 0.
// ep: 0 none | 1 leaky(acc+bias[n]) | 2 acc+B[K][n] | 3 acc+A[m][K]
//     4 fused SP+score: s = sum_n leaky(acc+bias[n]) * aux[(bz*L+y)*L*H + m*H + n],
//       16-lane reduce over n-threads, out[((bz*R+r)*L+m)*L+y] = s
//       where r = rz / L, y = rz % L. (BN must be 128; C is the out base.)
template <int BM, int BN, int OCC>
__global__ void __launch_bounds__((BM / 8) * (BN / 8), OCC) gemm6(
    const float* __restrict__ A, const float* __restrict__ B,
    float* __restrict__ C, int M, int N, int K, int lda, int ldb, int ldc,
    long long sA, long long sA2, long long sB, long long sB2, long long sC,
    int ZD, int ep, const float* __restrict__ bias,
    const float* __restrict__ aux) {
  constexpr int NT = (BM / 8) * (BN / 8);
  constexpr int AST = BM + 4;
  constexpr int AR = (BM * 32 + NT - 1) / NT;   // scalar A elems / thread
  constexpr int BR = (BN * 8 + NT - 1) / NT;    // float4 B vecs / thread
  extern __shared__ float smem[];
  float* As = smem;                 // [2][32][AST] transposed
  float* Bs = smem + 2 * 32 * AST;  // [2][32][BN]
  const int z = blockIdx.z;
  const int bz = z / ZD, rz = z % ZD;
  A += bz * sA + rz * sA2;
  B += bz * sB + rz * sB2;
  C += (long long)z * sC;
  const int tid = threadIdx.x;
  const int tx = tid % (BN / 8), ty = tid / (BN / 8);
  const int m0 = blockIdx.y * BM, n0 = blockIdx.x * BN;

  const uint32_t sbA = (uint32_t)__cvta_generic_to_shared(As);
  const uint32_t sbB = (uint32_t)__cvta_generic_to_shared(Bs);

  auto prefetch = [&](int k0, int s) {
#pragma unroll
    for (int t = 0; t < AR; ++t) {
      int idx = tid + t * NT;
      if (idx < BM * 32) {
        int m = idx >> 5, k = idx & 31;
        cp4(sbA + (((s * 32 + k) * AST + m) << 2),
            A + (long long)(m0 + m) * lda + k0 + k);
      }
    }
#pragma unroll
    for (int t = 0; t < BR; ++t) {
      int idx = tid + t * NT;
      if (idx < BN * 8) {
        int k = idx / (BN / 4), n4 = idx % (BN / 4);
        cp16(sbB + (((s * 32 + k) * BN + n4 * 4) << 2),
             B + (long long)(k0 + k) * ldb + n0 + n4 * 4);
      }
    }
  };

  float acc[8][8] = {};
  prefetch(0, 0);
  CP_COMMIT();
  int buf = 0;
  for (int k0 = 0; k0 < K; k0 += 32) {
    CP_WAIT0();
    __syncthreads();
    const bool next = (k0 + 32) < K;
    if (next) {
      prefetch(k0 + 32, buf ^ 1);
      CP_COMMIT();
    }
    const float* Ab = As + buf * 32 * AST;
    const float* Bb = Bs + buf * 32 * BN;
#pragma unroll 16
    for (int k = 0; k < 32; ++k) {
      float4 A0 = *(const float4*)(Ab + k * AST + ty * 4);
      float4 A1 = *(const float4*)(Ab + k * AST + BM / 2 + ty * 4);
      float4 B0 = *(const float4*)(Bb + k * BN + tx * 4);
      float4 B1 = *(const float4*)(Bb + k * BN + BN / 2 + tx * 4);
      float av[8] = {A0.x, A0.y, A0.z, A0.w, A1.x, A1.y, A1.z, A1.w};
      float bv[8] = {B0.x, B0.y, B0.z, B0.w, B1.x, B1.y, B1.z, B1.w};
#pragma unroll
      for (int i = 0; i < 8; ++i)
#pragma unroll
        for (int j = 0; j < 8; ++j)
          acc[i][j] = fmaf(av[i], bv[j], acc[i][j]);
    }
    buf ^= 1;
  }
  // ---------------- epilogues (tile-exact; no M/N guards) ----------------
  if (ep == 4) {  // fused SP + score; BN==128, n0==0, m0==0
    const int r = rz / L, y = rz % L;
    float4 bb0 = *(const float4*)(bias + tx * 4);
    float4 bb1 = *(const float4*)(bias + BN / 2 + tx * 4);
    const float* gbase = aux + ((long long)(bz * L + y) * L) * H;
#pragma unroll
    for (int i = 0; i < 8; ++i) {
      int m = (i < 4 ? ty * 4 + i : BM / 2 + ty * 4 + (i - 4));
      float4 g0 = *(const float4*)(gbase + (long long)m * H + tx * 4);
      float4 g1 = *(const float4*)(gbase + (long long)m * H + BN / 2 + tx * 4);
      float s = leaky(acc[i][0] + bb0.x) * g0.x + leaky(acc[i][1] + bb0.y) * g0.y +
                leaky(acc[i][2] + bb0.z) * g0.z + leaky(acc[i][3] + bb0.w) * g0.w +
                leaky(acc[i][4] + bb1.x) * g1.x + leaky(acc[i][5] + bb1.y) * g1.y +
                leaky(acc[i][6] + bb1.z) * g1.z + leaky(acc[i][7] + bb1.w) * g1.w;
#pragma unroll
      for (int o = 8; o; o >>= 1) s += __shfl_xor_sync(0xffffffffu, s, o);
      if (tx == 0)
        C[((long long)((bz * R + r) * L + m)) * L + y] = s;
    }
    return;
  }
  float4 br0 = make_float4(0.f, 0.f, 0.f, 0.f), br1 = br0;
  if (ep == 2) {  // pad row of B
    const float* Brow = B + (long long)K * ldb;
    br0 = *(const float4*)(Brow + n0 + tx * 4);
    br1 = *(const float4*)(Brow + n0 + BN / 2 + tx * 4);
  }
#pragma unroll
  for (int i = 0; i < 8; ++i) {
    int m = m0 + (i < 4 ? ty * 4 + i : BM / 2 + ty * 4 + (i - 4));
    float ra = (ep == 3) ? A[(long long)m * lda + K] : 0.f;
#pragma unroll
    for (int jh = 0; jh < 2; ++jh) {
      int n = n0 + (jh ? BN / 2 : 0) + tx * 4;
      float4 v = make_float4(acc[i][jh * 4 + 0], acc[i][jh * 4 + 1],
                             acc[i][jh * 4 + 2], acc[i][jh * 4 + 3]);
      if (ep == 1) {
        v.x = leaky(v.x + bias[n + 0]);
        v.y = leaky(v.y + bias[n + 1]);
        v.z = leaky(v.z + bias[n + 2]);
        v.w = leaky(v.w + bias[n + 3]);
      } else if (ep == 2) {
        float4 br = jh ? br1 : br0;
        v.x += br.x; v.y += br.y; v.z += br.z; v.w += br.w;
      } else if (ep == 3) {
        v.x += ra; v.y += ra; v.z += ra; v.w += ra;
      }
      *(float4*)(C + (long long)m * ldc + n) = v;
    }
  }
}

// ---------------- prep: inPT / xtailPT transposes ---------------------------
__global__ void k_prep2() {
  int t = blockIdx.x * blockDim.x + threadIdx.x;
  const int NPAD = BATCH * HP * L;  // 41280
  if (t < NPAD) {  // inPT[b][j][z]
    int b = t / (HP * L), rem = t % (HP * L);
    int j = rem / L, z = rem % L;
    g_inPT[t] = (j < H)
        ? g_hidden[(long long)(b * L + z) * (4 * H) + 3 * H + j] : 1.f;
    return;
  }
  t -= NPAD;
  if (t < NPAD) {  // xtailPT[b][m][y]
    int b = t / (HP * L), rem = t % (HP * L);
    int m = rem / L, y = rem % L;
    g_xtailPT[t] = (m < H)
        ? g_scoring[(long long)(b * L + y) * (2 * H) + H + m] : 1.f;
  }
}

// ---------------- softmax over last dim (160) (validated) -------------------
__global__ void k_softmax(float* __restrict__ lg, int nrows) {
  int w = (blockIdx.x * blockDim.x + threadIdx.x) >> 5;
  int lane = threadIdx.x & 31;
  if (w >= nrows) return;
  float* row = lg + (long long)w * L;
  float v[5];
  float mx = -1e30f;
#pragma unroll
  for (int t = 0; t < 5; ++t) {
    v[t] = row[t * 32 + lane];
    mx = fmaxf(mx, v[t]);
  }
#pragma unroll
  for (int o = 16; o; o >>= 1) mx = fmaxf(mx, __shfl_xor_sync(0xffffffffu, mx, o));
  float s = 0.f;
#pragma unroll
  for (int t = 0; t < 5; ++t) { v[t] = __expf(v[t] - mx); s += v[t]; }
#pragma unroll
  for (int o = 16; o; o >>= 1) s += __shfl_xor_sync(0xffffffffu, s, o);
  float inv = 1.f / s;
#pragma unroll
  for (int t = 0; t < 5; ++t) row[t * 32 + lane] = v[t] * inv;
}

// ---------------- Gt2[b][xq][y] -> Gt3[b][y][xq] (tiled transpose) ----------
__global__ void k_transpose(const float* __restrict__ in,
                            float* __restrict__ outp) {
  __shared__ float t[32][33];
  int b = blockIdx.z;
  int xq0 = blockIdx.x * 32, y0 = blockIdx.y * 32;
  const float* ip = in + (long long)b * (L * H) * L;
  float* op = outp + (long long)b * L * (L * H);
  int tx = threadIdx.x, ty0 = threadIdx.y;  // 32 x 8
  for (int i = ty0; i < 32; i += 8)
    t[i][tx] = ip[(long long)(xq0 + i) * L + (y0 + tx)];
  __syncthreads();
  for (int i = ty0; i < 32; i += 8)
    op[(long long)(y0 + i) * (L * H) + (xq0 + tx)] = t[tx][i];
}

// ------------------------------- launch --------------------------------------
static const float* pick_by_size(void* const* d_in, const int* in_sizes,
                                 int n_in, int want, int fallback_idx) {
  for (int i = 0; i < n_in; ++i)
    if (in_sizes[i] == want) return (const float*)d_in[i];
  return (const float*)d_in[fallback_idx];
}

extern "C" void kernel_launch(void* const* d_in, const int* in_sizes, int n_in,
                              void* d_out, int out_size) {
  (void)out_size;
  const float* x      = pick_by_size(d_in, in_sizes, n_in, BATCH * L * D, 0);
  const float* Wspan  = pick_by_size(d_in, in_sizes, n_in, D * 4 * H, 1);
  const float* bspan  = pick_by_size(d_in, in_sizes, n_in, 4 * H, 2);
  const float* Wscore = pick_by_size(d_in, in_sizes, n_in, D * 2 * H, 3);
  const float* bscore = pick_by_size(d_in, in_sizes, n_in, 2 * H, 4);
  const float* Wtri   = pick_by_size(d_in, in_sizes, n_in, R * HP * H * HP, 5);
  const float* Wmlp   = pick_by_size(d_in, in_sizes, n_in, H * H, 6);
  const float* bmlp   = pick_by_size(d_in, in_sizes, n_in, H, 7);
  const float* Wfin   = pick_by_size(d_in, in_sizes, n_in, HP * H * HP, 8);
  float* out = (float*)d_out;

  float* d_hidden;  cudaGetSymbolAddress((void**)&d_hidden, g_hidden);
  float* d_scoring; cudaGetSymbolAddress((void**)&d_scoring, g_scoring);
  float* d_inPT;    cudaGetSymbolAddress((void**)&d_inPT, g_inPT);
  float* d_xtailPT; cudaGetSymbolAddress((void**)&d_xtailPT, g_xtailPT);
  float* d_U;       cudaGetSymbolAddress((void**)&d_U, g_U);
  float* d_G;       cudaGetSymbolAddress((void**)&d_G, g_G);
  float* d_Gt2;     cudaGetSymbolAddress((void**)&d_Gt2, g_Gt2);
  float* d_Gt3;     cudaGetSymbolAddress((void**)&d_Gt3, g_Gt3);
  float* d_HRW;     cudaGetSymbolAddress((void**)&d_HRW, g_HRW);
  float* d_arena;   cudaGetSymbolAddress((void**)&d_arena, g_arena);
  float* d_W2 = d_arena + OFF_V;   // [b][(r,y)][k][z]
  float* d_LG = d_arena + OFF_LG;  // [b][(r,y)][x][z]

  cudaFuncSetAttribute(gemm6<160, 128, 2>,
                       cudaFuncAttributeMaxDynamicSharedMemorySize, SM_160_128);
  cudaFuncSetAttribute(gemm6<128, 160, 2>,
                       cudaFuncAttributeMaxDynamicSharedMemorySize, SM_128_160);
  cudaFuncSetAttribute(gemm6<80, 160, 3>,
                       cudaFuncAttributeMaxDynamicSharedMemorySize, SM_80_160);

  // 1) hidden = leaky(x @ Wspan + bspan)   [320,512], K=768
  gemm6<160, 128, 2><<<dim3(4, 2, 1), 320, SM_160_128>>>(
      x, Wspan, d_hidden, 320, 512, 768, 768, 512, 512,
      0, 0, 0, 0, 0, 1, 1, bspan, nullptr);
  // 2) scoring = leaky(x @ Wscore + bscore) [320,256], K=768
  gemm6<160, 128, 2><<<dim3(2, 2, 1), 320, SM_160_128>>>(
      x, Wscore, d_scoring, 320, 256, 768, 768, 256, 256,
      0, 0, 0, 0, 0, 1, 1, bscore, nullptr);
  // 3) transposes for inPT / xtailPT
  k_prep2<<<(2 * BATCH * HP * L + 255) / 256, 256>>>();
  // 4) U[(b,r)] = h_tail[b] @ Wtri[r][0:128] + Wtri[r][128]; z=(b,r), ZD=R
  gemm6<160, 128, 2><<<dim3(129, 1, BATCH * R), 320, SM_160_128>>>(
      d_hidden + 2 * H, Wtri, d_U, L, NKJ, H, 4 * H, NKJ, NKJ,
      (long long)L * (4 * H), 0, 0, WTRI_R, (long long)L * NKJ,
      R, 2, nullptr, nullptr);
  // 5) G[b] = x_head[b] @ Wfin[0:128] + Wfin[128]; z=b
  gemm6<160, 128, 2><<<dim3(129, 1, BATCH), 320, SM_160_128>>>(
      d_scoring, Wfin, d_G, L, NKJ, H, 2 * H, NKJ, NKJ,
      (long long)L * (2 * H), 0, 0, 0, (long long)L * NKJ,
      1, 2, nullptr, nullptr);
  // 6) Gt2[b] = G[b][:, 0:128] @ xtailPT[b][0:128] + G[..][128]; z=b
  gemm6<128, 160, 2><<<dim3(1, 160, BATCH), 320, SM_128_160>>>(
      d_G, d_xtailPT, d_Gt2, L * H, L, H, HP, L, L,
      (long long)L * NKJ, 0, (long long)HP * L, 0, (long long)(L * H) * L,
      1, 3, nullptr, nullptr);
  // 6b) Gt3[b][y][xq] = transpose(Gt2)
  k_transpose<<<dim3(640, 5, 2), dim3(32, 8)>>>(d_Gt2, d_Gt3);
  // 7) W2[z] = U[z][:, 0:128] @ inPT[b][0:128] + U[z][:, 128]; z=(b,(r,y))
  gemm6<128, 160, 2><<<dim3(1, 1, BATCH * R * L), 320, SM_128_160>>>(
      d_U, d_inPT, d_W2, H, L, H, HP, L, L,
      (long long)R * L * NKJ, NKJ, (long long)HP * L, 0, (long long)H * L,
      R * L, 3, nullptr, nullptr);
  // 8) logits[z] = h_head[b] [160,128] @ W2[z] [128,160]; z=(b,(r,y))
  gemm6<80, 160, 3><<<dim3(1, 2, BATCH * R * L), 200, SM_80_160>>>(
      d_hidden + H, d_W2, d_LG, L, L, H, 4 * H, L, L,
      (long long)L * (4 * H), 0, W2_B, (long long)H * L, (long long)L * L,
      R * L, 0, nullptr, nullptr);
  // 9) softmax over z (in place)
  {
    int nrows = BATCH * R * L * L;
    k_softmax<<<(nrows * 32 + 255) / 256, 256>>>(d_LG, nrows);
  }
  // 10) HRW[b] = h_in_repr[b] [160,128] @ Wmlp [128,128]; z=b
  gemm6<160, 128, 2><<<dim3(1, 1, BATCH), 320, SM_160_128>>>(
      d_hidden, Wmlp, d_HRW, L, H, H, 4 * H, H, H,
      (long long)L * (4 * H), 0, 0, 0, (long long)L * H,
      1, 0, nullptr, nullptr);
  // 11) fused: SP = leaky(alpha @ HRW + bmlp); out = sum_q SP*Gt3 (ep=4)
  gemm6<160, 128, 2><<<dim3(1, 1, BATCH * R * L), 320, SM_160_128>>>(
      d_LG, d_HRW, out, L, H, L, L, H, 0,
      LG_B, (long long)L * L, (long long)L * H, 0, 0,
      R * L, 4, bmlp, d_Gt3);
}